// round 2
// baseline (speedup 1.0000x reference)
#include <cuda_runtime.h>
#include <math.h>

#define B_   32
#define S_   577
#define D_   768
#define H_   12
#define DH_  64
#define M_   (B_ * S_)      // 18464
#define N3_  (3 * D_)       // 2304
#define SCALE_ 0.125f       // 1/sqrt(64)

// Scratch (device globals — allowed; no cudaMalloc)
__device__ float g_qkv[(size_t)M_ * N3_];   // [M, 3D] qkv projection output
__device__ float g_att[(size_t)M_ * D_];    // [M, D]  attention output

// ---------------------------------------------------------------------------
// SGEMM + bias: C[M,N] = A[M,K] @ B[K,N] + bias[N]
// BM=BN=128, BK=16, 256 threads, 8x8 per thread.
// Requires: N % 128 == 0, K % 16 == 0. M arbitrary (row-guarded).
// ---------------------------------------------------------------------------
__global__ __launch_bounds__(256) void sgemm_bias_kernel(
    const float* __restrict__ A, const float* __restrict__ Bm,
    const float* __restrict__ bias, float* __restrict__ C,
    int Mdim, int Ndim, int Kdim)
{
    __shared__ float As[16][128];   // transposed: As[k][m]
    __shared__ float Bs[16][128];   // Bs[k][n]

    const int tid = threadIdx.x;
    const int tx = tid & 15;        // 0..15 -> N
    const int ty = tid >> 4;        // 0..15 -> M
    const int row0 = blockIdx.y * 128;
    const int col0 = blockIdx.x * 128;

    float acc[8][8];
    #pragma unroll
    for (int i = 0; i < 8; ++i)
        #pragma unroll
        for (int j = 0; j < 8; ++j) acc[i][j] = 0.0f;

    const int nkt = Kdim >> 4;
    for (int kt = 0; kt < nkt; ++kt) {
        // Load A tile (128 x 16) as float4 along K, store transposed.
        #pragma unroll
        for (int u = 0; u < 2; ++u) {
            int f = tid + u * 256;          // 0..511 float4 slots
            int m = f >> 2;                 // 0..127
            int k4 = (f & 3) * 4;           // 0,4,8,12
            float4 v = make_float4(0.f, 0.f, 0.f, 0.f);
            int grow = row0 + m;
            if (grow < Mdim)
                v = *reinterpret_cast<const float4*>(
                        &A[(size_t)grow * Kdim + kt * 16 + k4]);
            As[k4 + 0][m] = v.x;
            As[k4 + 1][m] = v.y;
            As[k4 + 2][m] = v.z;
            As[k4 + 3][m] = v.w;
        }
        // Load B tile (16 x 128) as float4 along N.
        #pragma unroll
        for (int u = 0; u < 2; ++u) {
            int f = tid + u * 256;
            int k = f >> 5;                 // 0..15
            int n4 = (f & 31) * 4;          // 0..124
            float4 v = *reinterpret_cast<const float4*>(
                    &Bm[(size_t)(kt * 16 + k) * Ndim + col0 + n4]);
            *reinterpret_cast<float4*>(&Bs[k][n4]) = v;
        }
        __syncthreads();

        #pragma unroll
        for (int kk = 0; kk < 16; ++kk) {
            float a[8], b[8];
            *(float4*)&a[0] = *(const float4*)&As[kk][ty * 8];
            *(float4*)&a[4] = *(const float4*)&As[kk][ty * 8 + 4];
            *(float4*)&b[0] = *(const float4*)&Bs[kk][tx * 8];
            *(float4*)&b[4] = *(const float4*)&Bs[kk][tx * 8 + 4];
            #pragma unroll
            for (int i = 0; i < 8; ++i)
                #pragma unroll
                for (int j = 0; j < 8; ++j)
                    acc[i][j] += a[i] * b[j];
        }
        __syncthreads();
    }

    // Epilogue: bias + store (row-guarded).
    #pragma unroll
    for (int i = 0; i < 8; ++i) {
        int grow = row0 + ty * 8 + i;
        if (grow >= Mdim) continue;
        #pragma unroll
        for (int j4 = 0; j4 < 8; j4 += 4) {
            int gc = col0 + tx * 8 + j4;
            float4 o;
            o.x = acc[i][j4 + 0] + bias[gc + 0];
            o.y = acc[i][j4 + 1] + bias[gc + 1];
            o.z = acc[i][j4 + 2] + bias[gc + 2];
            o.w = acc[i][j4 + 3] + bias[gc + 3];
            *reinterpret_cast<float4*>(&C[(size_t)grow * Ndim + gc]) = o;
        }
    }
}

// ---------------------------------------------------------------------------
// Fused flash attention.
// Grid: (ceil(S/64), H, B). Block: (16,16). Each block: one 64-query tile of
// one (b,h). Online softmax across 64-key tiles. fp32 throughout.
// smem: Qt (d-major Q), KV (K transposed then V row-major, shared buffer),
//       Ps (probabilities, XOR-swizzled) -> exactly 48KB static.
// ---------------------------------------------------------------------------
__global__ __launch_bounds__(256) void attn_kernel(
    const float* __restrict__ qkv, float* __restrict__ outbuf)
{
    __shared__ float Qt[64 * 64];   // Qt[d*64 + s]
    __shared__ float KV[64 * 64];   // K phase: KV[d*64 + s]; V phase: KV[s*64 + d]
    __shared__ float Ps[64 * 64];   // Ps[q*64 + (k ^ (q&31))]

    const int tx = threadIdx.x;     // 0..15 -> key cols / out dims
    const int ty = threadIdx.y;     // 0..15 -> query rows
    const int tid = ty * 16 + tx;
    const int q0 = blockIdx.x * 64;
    const int h  = blockIdx.y;
    const int b  = blockIdx.z;

    // --- Load Q tile transposed: Qt[d][s_local] ---
    {
        int sl = tid >> 2;          // 0..63 local row
        int qu = tid & 3;           // quarter of the 64-dim row
        int sg = q0 + sl;
        #pragma unroll
        for (int c = 0; c < 4; ++c) {
            int d = qu * 16 + c * 4;
            float4 v = make_float4(0.f, 0.f, 0.f, 0.f);
            if (sg < S_)
                v = *reinterpret_cast<const float4*>(
                    &qkv[(size_t)(b * S_ + sg) * N3_ + h * 64 + d]);   // section 0 = Q
            Qt[(d + 0) * 64 + sl] = v.x;
            Qt[(d + 1) * 64 + sl] = v.y;
            Qt[(d + 2) * 64 + sl] = v.z;
            Qt[(d + 3) * 64 + sl] = v.w;
        }
    }

    float m[4], l[4], acc[4][4];
    #pragma unroll
    for (int i = 0; i < 4; ++i) {
        m[i] = -INFINITY;
        l[i] = 0.0f;
        #pragma unroll
        for (int j = 0; j < 4; ++j) acc[i][j] = 0.0f;
    }

    const int NT = (S_ + 63) / 64;  // 10 key tiles
    for (int t = 0; t < NT; ++t) {
        const int k0 = t * 64;

        // --- Load K tile transposed into KV: KV[d][s_local] ---
        {
            int sl = tid >> 2;
            int qu = tid & 3;
            int sg = k0 + sl;
            #pragma unroll
            for (int c = 0; c < 4; ++c) {
                int d = qu * 16 + c * 4;
                float4 v = make_float4(0.f, 0.f, 0.f, 0.f);
                if (sg < S_)
                    v = *reinterpret_cast<const float4*>(
                        &qkv[(size_t)(b * S_ + sg) * N3_ + D_ + h * 64 + d]);  // section 1 = K
                KV[(d + 0) * 64 + sl] = v.x;
                KV[(d + 1) * 64 + sl] = v.y;
                KV[(d + 2) * 64 + sl] = v.z;
                KV[(d + 3) * 64 + sl] = v.w;
            }
        }
        __syncthreads();   // Qt (first iter) + K ready; prior PV done reading Ps/KV

        // --- Scores: s[i][j] = sum_d Q[4ty+i][d] * K[4tx+j][d] ---
        float s[4][4];
        #pragma unroll
        for (int i = 0; i < 4; ++i)
            #pragma unroll
            for (int j = 0; j < 4; ++j) s[i][j] = 0.0f;

        #pragma unroll 16
        for (int d = 0; d < 64; ++d) {
            float4 a4 = *reinterpret_cast<const float4*>(&Qt[d * 64 + 4 * ty]);
            float4 b4 = *reinterpret_cast<const float4*>(&KV[d * 64 + 4 * tx]);
            float a[4] = {a4.x, a4.y, a4.z, a4.w};
            float bb[4] = {b4.x, b4.y, b4.z, b4.w};
            #pragma unroll
            for (int i = 0; i < 4; ++i)
                #pragma unroll
                for (int j = 0; j < 4; ++j)
                    s[i][j] += a[i] * bb[j];
        }

        // --- Scale + mask + online softmax update ---
        #pragma unroll
        for (int i = 0; i < 4; ++i) {
            #pragma unroll
            for (int j = 0; j < 4; ++j) {
                s[i][j] *= SCALE_;
                if (k0 + 4 * tx + j >= S_) s[i][j] = -1e30f;
            }
            // row max across this thread then across the 16 tx lanes
            float tm = fmaxf(fmaxf(s[i][0], s[i][1]), fmaxf(s[i][2], s[i][3]));
            #pragma unroll
            for (int off = 8; off >= 1; off >>= 1)
                tm = fmaxf(tm, __shfl_xor_sync(0xffffffffu, tm, off));
            float mnew = fmaxf(m[i], tm);
            float factor = __expf(m[i] - mnew);   // first iter: exp(-inf)=0
            float rsum = 0.0f;
            #pragma unroll
            for (int j = 0; j < 4; ++j) {
                s[i][j] = __expf(s[i][j] - mnew);  // now holds p
                rsum += s[i][j];
            }
            #pragma unroll
            for (int off = 8; off >= 1; off >>= 1)
                rsum += __shfl_xor_sync(0xffffffffu, rsum, off);
            l[i] = l[i] * factor + rsum;
            m[i] = mnew;
            #pragma unroll
            for (int j = 0; j < 4; ++j) acc[i][j] *= factor;
        }
        __syncthreads();   // all threads done reading KV(K) & old Ps

        // --- Write Ps (swizzled) + load V into KV row-major ---
        #pragma unroll
        for (int i = 0; i < 4; ++i) {
            int q = 4 * ty + i;
            #pragma unroll
            for (int j = 0; j < 4; ++j) {
                int kc = 4 * tx + j;
                Ps[q * 64 + (kc ^ (q & 31))] = s[i][j];
            }
        }
        {
            int sl = tid >> 2;
            int qu = tid & 3;
            int sg = k0 + sl;
            #pragma unroll
            for (int c = 0; c < 4; ++c) {
                int d = qu * 16 + c * 4;
                float4 v = make_float4(0.f, 0.f, 0.f, 0.f);
                if (sg < S_)
                    v = *reinterpret_cast<const float4*>(
                        &qkv[(size_t)(b * S_ + sg) * N3_ + 2 * D_ + h * 64 + d]); // section 2 = V
                *reinterpret_cast<float4*>(&KV[sl * 64 + d]) = v;
            }
        }
        __syncthreads();

        // --- PV: acc[i][j] += sum_k P[q][k] * V[k][4tx+j] ---
        #pragma unroll 16
        for (int k = 0; k < 64; ++k) {
            float a[4];
            #pragma unroll
            for (int i = 0; i < 4; ++i) {
                int q = 4 * ty + i;
                a[i] = Ps[q * 64 + (k ^ (q & 31))];
            }
            float4 b4 = *reinterpret_cast<const float4*>(&KV[k * 64 + 4 * tx]);
            float bb[4] = {b4.x, b4.y, b4.z, b4.w};
            #pragma unroll
            for (int i = 0; i < 4; ++i)
                #pragma unroll
                for (int j = 0; j < 4; ++j)
                    acc[i][j] += a[i] * bb[j];
        }
        __syncthreads();   // before next tile overwrites KV
    }

    // --- Normalize + store: outbuf[(b*S+q)*D + h*64 + d] ---
    #pragma unroll
    for (int i = 0; i < 4; ++i) {
        int q = q0 + 4 * ty + i;
        if (q >= S_) continue;
        float inv = 1.0f / l[i];
        float4 o;
        o.x = acc[i][0] * inv;
        o.y = acc[i][1] * inv;
        o.z = acc[i][2] * inv;
        o.w = acc[i][3] * inv;
        *reinterpret_cast<float4*>(
            &outbuf[(size_t)(b * S_ + q) * D_ + h * 64 + 4 * tx]) = o;
    }
}

// ---------------------------------------------------------------------------
extern "C" void kernel_launch(void* const* d_in, const int* in_sizes, int n_in,
                              void* d_out, int out_size)
{
    const float* x     = (const float*)d_in[0];
    const float* w_qkv = (const float*)d_in[1];
    const float* b_qkv = (const float*)d_in[2];
    const float* w_fc  = (const float*)d_in[3];
    const float* b_fc  = (const float*)d_in[4];
    float* out = (float*)d_out;

    float* qkv = nullptr;
    float* att = nullptr;
    cudaGetSymbolAddress((void**)&qkv, g_qkv);
    cudaGetSymbolAddress((void**)&att, g_att);

    // 1) QKV projection: [M, 3D] = x[M, D] @ w_qkv[D, 3D] + b_qkv
    sgemm_bias_kernel<<<dim3(N3_ / 128, (M_ + 127) / 128), 256>>>(
        x, w_qkv, b_qkv, qkv, M_, N3_, D_);

    // 2) Fused multi-head flash attention -> att [M, D]
    attn_kernel<<<dim3((S_ + 63) / 64, H_, B_), dim3(16, 16)>>>(qkv, att);

    // 3) Output projection: out = att @ w_fc + b_fc
    sgemm_bias_kernel<<<dim3(D_ / 128, (M_ + 127) / 128), 256>>>(
        att, w_fc, b_fc, out, M_, D_, D_);
}

// round 7
// speedup vs baseline: 1.4075x; 1.4075x over previous
#include <cuda_runtime.h>
#include <cuda_bf16.h>
#include <math.h>
#include <cstdint>

#define B_   32
#define S_   577
#define D_   768
#define H_   12
#define M_   (B_ * S_)      // 18464
#define N3_  (3 * D_)       // 2304
#define SCALE_ 0.125f       // 1/sqrt(64)

// ---------------- scratch (device globals; no cudaMalloc) -------------------
__device__ float g_qkv[(size_t)M_ * N3_];
__device__ float g_att[(size_t)M_ * D_];
__device__ __nv_bfloat16 g_xhi[(size_t)M_ * D_];
__device__ __nv_bfloat16 g_xlo[(size_t)M_ * D_];
__device__ __nv_bfloat16 g_ahi[(size_t)M_ * D_];
__device__ __nv_bfloat16 g_alo[(size_t)M_ * D_];
__device__ __nv_bfloat16 g_wqhiT[(size_t)N3_ * D_];   // w_qkv^T [N,K]
__device__ __nv_bfloat16 g_wqloT[(size_t)N3_ * D_];
__device__ __nv_bfloat16 g_wfhiT[(size_t)D_ * D_];    // w_fc^T [N,K]
__device__ __nv_bfloat16 g_wfloT[(size_t)D_ * D_];

// ---------------- base-ISA PTX helpers --------------------------------------
__device__ __forceinline__ uint32_t smem_u32(const void* p) {
    uint32_t a;
    asm("{ .reg .u64 t; cvta.to.shared.u64 t, %1; cvt.u32.u64 %0, t; }"
        : "=r"(a) : "l"(p));
    return a;
}
__device__ __forceinline__ void cp_async16(uint32_t dst, const void* src, int sz) {
    asm volatile("cp.async.cg.shared.global [%0], [%1], 16, %2;"
                 :: "r"(dst), "l"(src), "r"(sz) : "memory");
}
__device__ __forceinline__ void cp_commit() {
    asm volatile("cp.async.commit_group;" ::: "memory");
}
template <int N>
__device__ __forceinline__ void cp_wait() {
    asm volatile("cp.async.wait_group %0;" :: "n"(N) : "memory");
}
__device__ __forceinline__ void ldsm_x4(uint32_t& r0, uint32_t& r1,
                                        uint32_t& r2, uint32_t& r3, uint32_t a) {
    asm volatile("ldmatrix.sync.aligned.m8n8.x4.shared.b16 {%0,%1,%2,%3}, [%4];"
                 : "=r"(r0), "=r"(r1), "=r"(r2), "=r"(r3) : "r"(a));
}
__device__ __forceinline__ void mma_bf16(float* c, const uint32_t* a,
                                         const uint32_t* b) {
    asm volatile(
        "mma.sync.aligned.m16n8k16.row.col.f32.bf16.bf16.f32 "
        "{%0,%1,%2,%3}, {%4,%5,%6,%7}, {%8,%9}, {%0,%1,%2,%3};"
        : "+f"(c[0]), "+f"(c[1]), "+f"(c[2]), "+f"(c[3])
        : "r"(a[0]), "r"(a[1]), "r"(a[2]), "r"(a[3]), "r"(b[0]), "r"(b[1]));
}

// smem tile layout: 128 rows x 64B (32 bf16). XOR swizzle keeps both the 16B
// cp.async stores and the LDSM 8-address phases bank-conflict-free.
__device__ __forceinline__ uint32_t tile_off(int r, int c) {
    return (uint32_t)(r * 64 + ((c ^ ((r >> 1) & 3)) << 4));
}

// ---------------- conversion kernels ---------------------------------------
__global__ void split_kernel(const float* __restrict__ src,
                             __nv_bfloat16* __restrict__ hi,
                             __nv_bfloat16* __restrict__ lo, int n4)
{
    int i = blockIdx.x * blockDim.x + threadIdx.x;
    if (i >= n4) return;
    float4 v = reinterpret_cast<const float4*>(src)[i];
    float xs[4] = {v.x, v.y, v.z, v.w};
    #pragma unroll
    for (int j = 0; j < 4; ++j) {
        __nv_bfloat16 h = __float2bfloat16(xs[j]);
        hi[i * 4 + j] = h;
        lo[i * 4 + j] = __float2bfloat16(xs[j] - __bfloat162float(h));
    }
}

__global__ void wsplit_kernel(const float* __restrict__ w,
                              __nv_bfloat16* __restrict__ hiT,
                              __nv_bfloat16* __restrict__ loT, int K, int N)
{
    int idx = blockIdx.x * blockDim.x + threadIdx.x;
    if (idx >= N * K) return;
    int n = idx / K, k = idx - n * K;
    float x = w[(size_t)k * N + n];
    __nv_bfloat16 h = __float2bfloat16(x);
    hiT[idx] = h;
    loT[idx] = __float2bfloat16(x - __bfloat162float(h));
}

// ---------------------------------------------------------------------------
// Tensor-core GEMM (mma.sync bf16, 3-term split):
//   C[M,N] = (Ahi+Alo)[M,K] @ (Bhi+Blo)[N,K]^T + bias
// CTA 128x128, BK=32, 256 thr (8 warps, 2x4 of 64x32), 2-stage cp.async.
// ---------------------------------------------------------------------------
#define STAGE_BYTES 32768           // 4 tiles x 128 rows x 64B
#define GEMM_SMEM   (2 * STAGE_BYTES)

__global__ __launch_bounds__(256) void gemm_tc_kernel(
    const __nv_bfloat16* __restrict__ Ahi, const __nv_bfloat16* __restrict__ Alo,
    const __nv_bfloat16* __restrict__ Bhi, const __nv_bfloat16* __restrict__ Blo,
    const float* __restrict__ bias, float* __restrict__ C,
    int Mdim, int Ndim, int Kdim)
{
    extern __shared__ char smem[];
    const uint32_t sbase = smem_u32(smem);
    const int tid = threadIdx.x;
    const int wid = tid >> 5, lid = tid & 31;
    const int wr = wid >> 2;            // 0..1 -> M offset wr*64
    const int wc = wid & 3;             // 0..3 -> N offset wc*32
    const int row0 = blockIdx.y * 128, col0 = blockIdx.x * 128;

    // stage s offsets: AHI, ALO, BHI, BLO tiles of 8KB each
    auto stage_base = [&](int s) -> uint32_t { return sbase + s * STAGE_BYTES; };

    // ---- async tile loader: 2 x 16B per thread per tile -------------------
    auto load_stage = [&](int s, int k0) {
        uint32_t sb = stage_base(s);
        #pragma unroll
        for (int i = 0; i < 2; ++i) {
            int slot = tid + i * 256;       // 0..511
            int r = slot >> 2;              // 0..127
            int c = slot & 3;               // 16B chunk
            uint32_t so = tile_off(r, c);
            int ga = row0 + r;
            int szA = (ga < Mdim) ? 16 : 0;
            const __nv_bfloat16* pAh = Ahi + (size_t)(szA ? ga : 0) * Kdim + k0 + c * 8;
            const __nv_bfloat16* pAl = Alo + (size_t)(szA ? ga : 0) * Kdim + k0 + c * 8;
            cp_async16(sb + so,                 pAh, szA);
            cp_async16(sb + 8192 + so,          pAl, szA);
            const __nv_bfloat16* pBh = Bhi + (size_t)(col0 + r) * Kdim + k0 + c * 8;
            const __nv_bfloat16* pBl = Blo + (size_t)(col0 + r) * Kdim + k0 + c * 8;
            cp_async16(sb + 16384 + so,         pBh, 16);
            cp_async16(sb + 24576 + so,         pBl, 16);
        }
    };

    float acc[4][4][4];                 // [mtile][ntile][frag]
    #pragma unroll
    for (int i = 0; i < 4; ++i)
        #pragma unroll
        for (int j = 0; j < 4; ++j)
            #pragma unroll
            for (int e = 0; e < 4; ++e) acc[i][j][e] = 0.0f;

    // per-lane ldmatrix row components (row part fixed across steps)
    const int lrow = lid & 15;          // row within 16-row group
    const int lhi  = lid >> 4;          // 0: k-lo chunk, 1: k-hi chunk

    const int nck = Kdim >> 5;          // BK=32 chunks
    load_stage(0, 0);
    cp_commit();

    for (int ck = 0; ck < nck; ++ck) {
        if (ck + 1 < nck) { load_stage((ck + 1) & 1, (ck + 1) << 5); cp_commit(); }
        if (ck + 1 < nck) cp_wait<1>(); else cp_wait<0>();
        __syncthreads();

        const uint32_t sb = stage_base(ck & 1);
        const uint32_t bAhi = sb, bAlo = sb + 8192;
        const uint32_t bBhi = sb + 16384, bBlo = sb + 24576;

        #pragma unroll
        for (int s = 0; s < 2; ++s) {   // two k16 steps
            const int cch = 2 * s + lhi;
            uint32_t ah[4][4], al[4][4], bh[2][4], bl[2][4];

            // A rows for this warp: wr*64 + mt*16 + lrow
            #pragma unroll
            for (int mt = 0; mt < 4; ++mt) {
                int r = wr * 64 + mt * 16 + lrow;
                uint32_t o = tile_off(r, cch);
                ldsm_x4(ah[mt][0], ah[mt][1], ah[mt][2], ah[mt][3], bAhi + o);
            }
            // B rows: wc*32 + g*16 + lrow
            #pragma unroll
            for (int g = 0; g < 2; ++g) {
                int r = wc * 32 + g * 16 + lrow;
                uint32_t o = tile_off(r, cch);
                ldsm_x4(bh[g][0], bh[g][1], bh[g][2], bh[g][3], bBhi + o);
            }
            // hi*hi
            #pragma unroll
            for (int mt = 0; mt < 4; ++mt)
                #pragma unroll
                for (int nt = 0; nt < 4; ++nt) {
                    uint32_t bb[2] = { bh[nt >> 1][nt & 1], bh[nt >> 1][(nt & 1) + 2] };
                    mma_bf16(acc[mt][nt], ah[mt], bb);
                }
            // lo*hi
            #pragma unroll
            for (int mt = 0; mt < 4; ++mt) {
                int r = wr * 64 + mt * 16 + lrow;
                uint32_t o = tile_off(r, cch);
                ldsm_x4(al[mt][0], al[mt][1], al[mt][2], al[mt][3], bAlo + o);
            }
            #pragma unroll
            for (int mt = 0; mt < 4; ++mt)
                #pragma unroll
                for (int nt = 0; nt < 4; ++nt) {
                    uint32_t bb[2] = { bh[nt >> 1][nt & 1], bh[nt >> 1][(nt & 1) + 2] };
                    mma_bf16(acc[mt][nt], al[mt], bb);
                }
            // hi*lo
            #pragma unroll
            for (int g = 0; g < 2; ++g) {
                int r = wc * 32 + g * 16 + lrow;
                uint32_t o = tile_off(r, cch);
                ldsm_x4(bl[g][0], bl[g][1], bl[g][2], bl[g][3], bBlo + o);
            }
            #pragma unroll
            for (int mt = 0; mt < 4; ++mt)
                #pragma unroll
                for (int nt = 0; nt < 4; ++nt) {
                    uint32_t bb[2] = { bl[nt >> 1][nt & 1], bl[nt >> 1][(nt & 1) + 2] };
                    mma_bf16(acc[mt][nt], ah[mt], bb);
                }
        }
        __syncthreads();   // before next iteration's loads overwrite this stage
    }

    // ---- epilogue: bias + store -------------------------------------------
    const int g4 = lid >> 2, t4 = lid & 3;
    #pragma unroll
    for (int mt = 0; mt < 4; ++mt) {
        #pragma unroll
        for (int half = 0; half < 2; ++half) {
            int grow = row0 + wr * 64 + mt * 16 + g4 + half * 8;
            if (grow >= Mdim) continue;
            #pragma unroll
            for (int nt = 0; nt < 4; ++nt) {
                int gc = col0 + wc * 32 + nt * 8 + t4 * 2;
                float2 o;
                o.x = acc[mt][nt][half * 2 + 0] + bias[gc + 0];
                o.y = acc[mt][nt][half * 2 + 1] + bias[gc + 1];
                *reinterpret_cast<float2*>(&C[(size_t)grow * Ndim + gc]) = o;
            }
        }
    }
}

// ---------------------------------------------------------------------------
// Fused flash attention (unchanged — fp32, passed at 5.3e-7)
// ---------------------------------------------------------------------------
__global__ __launch_bounds__(256) void attn_kernel(
    const float* __restrict__ qkv, float* __restrict__ outbuf)
{
    __shared__ float Qt[64 * 64];
    __shared__ float KV[64 * 64];
    __shared__ float Ps[64 * 64];

    const int tx = threadIdx.x;
    const int ty = threadIdx.y;
    const int tid = ty * 16 + tx;
    const int q0 = blockIdx.x * 64;
    const int h  = blockIdx.y;
    const int b  = blockIdx.z;

    {
        int sl = tid >> 2, qu = tid & 3;
        int sg = q0 + sl;
        #pragma unroll
        for (int c = 0; c < 4; ++c) {
            int d = qu * 16 + c * 4;
            float4 v = make_float4(0.f, 0.f, 0.f, 0.f);
            if (sg < S_)
                v = *reinterpret_cast<const float4*>(
                    &qkv[(size_t)(b * S_ + sg) * N3_ + h * 64 + d]);
            Qt[(d + 0) * 64 + sl] = v.x;
            Qt[(d + 1) * 64 + sl] = v.y;
            Qt[(d + 2) * 64 + sl] = v.z;
            Qt[(d + 3) * 64 + sl] = v.w;
        }
    }

    float m[4], l[4], acc[4][4];
    #pragma unroll
    for (int i = 0; i < 4; ++i) {
        m[i] = -INFINITY; l[i] = 0.0f;
        #pragma unroll
        for (int j = 0; j < 4; ++j) acc[i][j] = 0.0f;
    }

    const int NT = (S_ + 63) / 64;
    for (int t = 0; t < NT; ++t) {
        const int k0 = t * 64;
        {
            int sl = tid >> 2, qu = tid & 3;
            int sg = k0 + sl;
            #pragma unroll
            for (int c = 0; c < 4; ++c) {
                int d = qu * 16 + c * 4;
                float4 v = make_float4(0.f, 0.f, 0.f, 0.f);
                if (sg < S_)
                    v = *reinterpret_cast<const float4*>(
                        &qkv[(size_t)(b * S_ + sg) * N3_ + D_ + h * 64 + d]);
                KV[(d + 0) * 64 + sl] = v.x;
                KV[(d + 1) * 64 + sl] = v.y;
                KV[(d + 2) * 64 + sl] = v.z;
                KV[(d + 3) * 64 + sl] = v.w;
            }
        }
        __syncthreads();

        float s[4][4];
        #pragma unroll
        for (int i = 0; i < 4; ++i)
            #pragma unroll
            for (int j = 0; j < 4; ++j) s[i][j] = 0.0f;

        #pragma unroll 16
        for (int d = 0; d < 64; ++d) {
            float4 a4 = *reinterpret_cast<const float4*>(&Qt[d * 64 + 4 * ty]);
            float4 b4 = *reinterpret_cast<const float4*>(&KV[d * 64 + 4 * tx]);
            float a[4] = {a4.x, a4.y, a4.z, a4.w};
            float bb[4] = {b4.x, b4.y, b4.z, b4.w};
            #pragma unroll
            for (int i = 0; i < 4; ++i)
                #pragma unroll
                for (int j = 0; j < 4; ++j)
                    s[i][j] += a[i] * bb[j];
        }

        #pragma unroll
        for (int i = 0; i < 4; ++i) {
            #pragma unroll
            for (int j = 0; j < 4; ++j) {
                s[i][j] *= SCALE_;
                if (k0 + 4 * tx + j >= S_) s[i][j] = -1e30f;
            }
            float tm = fmaxf(fmaxf(s[i][0], s[i][1]), fmaxf(s[i][2], s[i][3]));
            #pragma unroll
            for (int off = 8; off >= 1; off >>= 1)
                tm = fmaxf(tm, __shfl_xor_sync(0xffffffffu, tm, off));
            float mnew = fmaxf(m[i], tm);
            float factor = __expf(m[i] - mnew);
            float rsum = 0.0f;
            #pragma unroll
            for (int j = 0; j < 4; ++j) {
                s[i][j] = __expf(s[i][j] - mnew);
                rsum += s[i][j];
            }
            #pragma unroll
            for (int off = 8; off >= 1; off >>= 1)
                rsum += __shfl_xor_sync(0xffffffffu, rsum, off);
            l[i] = l[i] * factor + rsum;
            m[i] = mnew;
            #pragma unroll
            for (int j = 0; j < 4; ++j) acc[i][j] *= factor;
        }
        __syncthreads();

        #pragma unroll
        for (int i = 0; i < 4; ++i) {
            int q = 4 * ty + i;
            #pragma unroll
            for (int j = 0; j < 4; ++j) {
                int kc = 4 * tx + j;
                Ps[q * 64 + (kc ^ (q & 31))] = s[i][j];
            }
        }
        {
            int sl = tid >> 2, qu = tid & 3;
            int sg = k0 + sl;
            #pragma unroll
            for (int c = 0; c < 4; ++c) {
                int d = qu * 16 + c * 4;
                float4 v = make_float4(0.f, 0.f, 0.f, 0.f);
                if (sg < S_)
                    v = *reinterpret_cast<const float4*>(
                        &qkv[(size_t)(b * S_ + sg) * N3_ + 2 * D_ + h * 64 + d]);
                *reinterpret_cast<float4*>(&KV[sl * 64 + d]) = v;
            }
        }
        __syncthreads();

        #pragma unroll 16
        for (int k = 0; k < 64; ++k) {
            float a[4];
            #pragma unroll
            for (int i = 0; i < 4; ++i) {
                int q = 4 * ty + i;
                a[i] = Ps[q * 64 + (k ^ (q & 31))];
            }
            float4 b4 = *reinterpret_cast<const float4*>(&KV[k * 64 + 4 * tx]);
            float bb[4] = {b4.x, b4.y, b4.z, b4.w};
            #pragma unroll
            for (int i = 0; i < 4; ++i)
                #pragma unroll
                for (int j = 0; j < 4; ++j)
                    acc[i][j] += a[i] * bb[j];
        }
        __syncthreads();
    }

    #pragma unroll
    for (int i = 0; i < 4; ++i) {
        int q = q0 + 4 * ty + i;
        if (q >= S_) continue;
        float inv = 1.0f / l[i];
        float4 o;
        o.x = acc[i][0] * inv;
        o.y = acc[i][1] * inv;
        o.z = acc[i][2] * inv;
        o.w = acc[i][3] * inv;
        *reinterpret_cast<float4*>(
            &outbuf[(size_t)(b * S_ + q) * D_ + h * 64 + 4 * tx]) = o;
    }
}

// ---------------------------------------------------------------------------
extern "C" void kernel_launch(void* const* d_in, const int* in_sizes, int n_in,
                              void* d_out, int out_size)
{
    const float* x     = (const float*)d_in[0];
    const float* w_qkv = (const float*)d_in[1];
    const float* b_qkv = (const float*)d_in[2];
    const float* w_fc  = (const float*)d_in[3];
    const float* b_fc  = (const float*)d_in[4];
    float* out = (float*)d_out;

    float *qkv, *att;
    __nv_bfloat16 *xhi, *xlo, *ahi, *alo, *wqh, *wql, *wfh, *wfl;
    cudaGetSymbolAddress((void**)&qkv, g_qkv);
    cudaGetSymbolAddress((void**)&att, g_att);
    cudaGetSymbolAddress((void**)&xhi, g_xhi);
    cudaGetSymbolAddress((void**)&xlo, g_xlo);
    cudaGetSymbolAddress((void**)&ahi, g_ahi);
    cudaGetSymbolAddress((void**)&alo, g_alo);
    cudaGetSymbolAddress((void**)&wqh, g_wqhiT);
    cudaGetSymbolAddress((void**)&wql, g_wqloT);
    cudaGetSymbolAddress((void**)&wfh, g_wfhiT);
    cudaGetSymbolAddress((void**)&wfl, g_wfloT);

    static bool attr_set = false;
    if (!attr_set) {
        cudaFuncSetAttribute(gemm_tc_kernel,
                             cudaFuncAttributeMaxDynamicSharedMemorySize,
                             GEMM_SMEM);
        attr_set = true;
    }

    // 0) Precision-split conversions
    {
        int n4 = (M_ * D_) / 4;
        split_kernel<<<(n4 + 255) / 256, 256>>>(x, xhi, xlo, n4);
    }
    wsplit_kernel<<<(N3_ * D_ + 255) / 256, 256>>>(w_qkv, wqh, wql, D_, N3_);
    wsplit_kernel<<<(D_ * D_ + 255) / 256, 256>>>(w_fc, wfh, wfl, D_, D_);

    // 1) QKV projection (tensor cores): [M,3D] = x @ w_qkv + b_qkv
    gemm_tc_kernel<<<dim3(N3_ / 128, (M_ + 127) / 128), 256, GEMM_SMEM>>>(
        xhi, xlo, wqh, wql, b_qkv, qkv, M_, N3_, D_);

    // 2) Fused multi-head flash attention -> att [M,D]
    attn_kernel<<<dim3((S_ + 63) / 64, H_, B_), dim3(16, 16)>>>(qkv, att);

    // 2b) Split attention output for FC GEMM
    {
        int n4 = (M_ * D_) / 4;
        split_kernel<<<(n4 + 255) / 256, 256>>>(att, ahi, alo, n4);
    }

    // 3) Output projection (tensor cores): out = att @ w_fc + b_fc
    gemm_tc_kernel<<<dim3(D_ / 128, (M_ + 127) / 128), 256, GEMM_SMEM>>>(
        ahi, alo, wfh, wfl, b_fc, out, M_, D_, D_);
}

// round 11
// speedup vs baseline: 2.6404x; 1.8760x over previous
#include <cuda_runtime.h>
#include <cuda_bf16.h>
#include <math.h>
#include <cstdint>

#define B_   32
#define S_   577
#define D_   768
#define H_   12
#define M_   (B_ * S_)      // 18464
#define N3_  (3 * D_)       // 2304
#define SCALE_ 0.125f       // 1/sqrt(64)

// ---------------- scratch (device globals; no cudaMalloc) -------------------
__device__ __nv_bfloat16 g_xhi[(size_t)M_ * D_];
__device__ __nv_bfloat16 g_xlo[(size_t)M_ * D_];
__device__ __nv_bfloat16 g_qkvhi[(size_t)M_ * N3_];   // qkv projection (hi)
__device__ __nv_bfloat16 g_qkvlo[(size_t)M_ * N3_];   // qkv projection (lo)
__device__ __nv_bfloat16 g_atthi[(size_t)M_ * D_];    // attention out (hi)
__device__ __nv_bfloat16 g_attlo[(size_t)M_ * D_];    // attention out (lo)
__device__ __nv_bfloat16 g_wqhiT[(size_t)N3_ * D_];   // w_qkv^T [N,K]
__device__ __nv_bfloat16 g_wqloT[(size_t)N3_ * D_];
__device__ __nv_bfloat16 g_wfhiT[(size_t)D_ * D_];    // w_fc^T [N,K]
__device__ __nv_bfloat16 g_wfloT[(size_t)D_ * D_];

// ---------------- base-ISA PTX helpers --------------------------------------
__device__ __forceinline__ uint32_t smem_u32(const void* p) {
    uint32_t a;
    asm("{ .reg .u64 t; cvta.to.shared.u64 t, %1; cvt.u32.u64 %0, t; }"
        : "=r"(a) : "l"(p));
    return a;
}
__device__ __forceinline__ void cp_async16(uint32_t dst, const void* src, int sz) {
    asm volatile("cp.async.cg.shared.global [%0], [%1], 16, %2;"
                 :: "r"(dst), "l"(src), "r"(sz) : "memory");
}
__device__ __forceinline__ void cp_commit() {
    asm volatile("cp.async.commit_group;" ::: "memory");
}
template <int N>
__device__ __forceinline__ void cp_wait() {
    asm volatile("cp.async.wait_group %0;" :: "n"(N) : "memory");
}
__device__ __forceinline__ void ldsm_x4(uint32_t& r0, uint32_t& r1,
                                        uint32_t& r2, uint32_t& r3, uint32_t a) {
    asm volatile("ldmatrix.sync.aligned.m8n8.x4.shared.b16 {%0,%1,%2,%3}, [%4];"
                 : "=r"(r0), "=r"(r1), "=r"(r2), "=r"(r3) : "r"(a));
}
__device__ __forceinline__ void ldsm_x4_t(uint32_t& r0, uint32_t& r1,
                                          uint32_t& r2, uint32_t& r3, uint32_t a) {
    asm volatile("ldmatrix.sync.aligned.m8n8.x4.trans.shared.b16 {%0,%1,%2,%3}, [%4];"
                 : "=r"(r0), "=r"(r1), "=r"(r2), "=r"(r3) : "r"(a));
}
__device__ __forceinline__ void mma_bf16(float* c, const uint32_t* a,
                                         const uint32_t* b) {
    asm volatile(
        "mma.sync.aligned.m16n8k16.row.col.f32.bf16.bf16.f32 "
        "{%0,%1,%2,%3}, {%4,%5,%6,%7}, {%8,%9}, {%0,%1,%2,%3};"
        : "+f"(c[0]), "+f"(c[1]), "+f"(c[2]), "+f"(c[3])
        : "r"(a[0]), "r"(a[1]), "r"(a[2]), "r"(a[3]), "r"(b[0]), "r"(b[1]));
}

// split fp32 pair -> packed bf16x2 hi and lo-residual
__device__ __forceinline__ void split_pack2(float a, float b,
                                            uint32_t& hi, uint32_t& lo) {
    __nv_bfloat16 ah = __float2bfloat16(a);
    __nv_bfloat16 bh = __float2bfloat16(b);
    __nv_bfloat16 al = __float2bfloat16(a - __bfloat162float(ah));
    __nv_bfloat16 bl = __float2bfloat16(b - __bfloat162float(bh));
    __nv_bfloat162 h2 = __nv_bfloat162(ah, bh);
    __nv_bfloat162 l2 = __nv_bfloat162(al, bl);
    hi = *reinterpret_cast<uint32_t*>(&h2);
    lo = *reinterpret_cast<uint32_t*>(&l2);
}

// 64B-row tile swizzle (GEMM tiles)
__device__ __forceinline__ uint32_t tile_off(int r, int c) {
    return (uint32_t)(r * 64 + ((c ^ ((r >> 1) & 3)) << 4));
}
// 128B-row tile swizzle (attention tiles): r<128, 16B chunk c<8
__device__ __forceinline__ uint32_t soff(int r, int c) {
    return (uint32_t)((r << 7) + (((c ^ (r & 7)) & 7) << 4));
}

// ---------------- conversion kernels ---------------------------------------
__global__ void split_kernel(const float* __restrict__ src,
                             __nv_bfloat16* __restrict__ hi,
                             __nv_bfloat16* __restrict__ lo, int n4)
{
    int i = blockIdx.x * blockDim.x + threadIdx.x;
    if (i >= n4) return;
    float4 v = reinterpret_cast<const float4*>(src)[i];
    float xs[4] = {v.x, v.y, v.z, v.w};
    #pragma unroll
    for (int j = 0; j < 4; ++j) {
        __nv_bfloat16 h = __float2bfloat16(xs[j]);
        hi[i * 4 + j] = h;
        lo[i * 4 + j] = __float2bfloat16(xs[j] - __bfloat162float(h));
    }
}

__global__ void wsplit_kernel(const float* __restrict__ w,
                              __nv_bfloat16* __restrict__ hiT,
                              __nv_bfloat16* __restrict__ loT, int K, int N)
{
    int idx = blockIdx.x * blockDim.x + threadIdx.x;
    if (idx >= N * K) return;
    int n = idx / K, k = idx - n * K;
    float x = w[(size_t)k * N + n];
    __nv_bfloat16 h = __float2bfloat16(x);
    hiT[idx] = h;
    loT[idx] = __float2bfloat16(x - __bfloat162float(h));
}

// ---------------------------------------------------------------------------
// Tensor-core GEMM (mma.sync bf16, 3-term split):
//   C = (Ahi+Alo)[M,K] @ (Bhi+Blo)[N,K]^T + bias
// Output: fp32 C (if Chi==null) or bf16 hi/lo pair (Chi/Clo).
// ---------------------------------------------------------------------------
#define STAGE_BYTES 32768
#define GEMM_SMEM   (2 * STAGE_BYTES)

__global__ __launch_bounds__(256) void gemm_tc_kernel(
    const __nv_bfloat16* __restrict__ Ahi, const __nv_bfloat16* __restrict__ Alo,
    const __nv_bfloat16* __restrict__ Bhi, const __nv_bfloat16* __restrict__ Blo,
    const float* __restrict__ bias, float* __restrict__ C,
    __nv_bfloat16* __restrict__ Chi, __nv_bfloat16* __restrict__ Clo,
    int Mdim, int Ndim, int Kdim)
{
    extern __shared__ char smem[];
    const uint32_t sbase = smem_u32(smem);
    const int tid = threadIdx.x;
    const int wid = tid >> 5, lid = tid & 31;
    const int wr = wid >> 2;
    const int wc = wid & 3;
    const int row0 = blockIdx.y * 128, col0 = blockIdx.x * 128;

    auto stage_base = [&](int s) -> uint32_t { return sbase + s * STAGE_BYTES; };

    auto load_stage = [&](int s, int k0) {
        uint32_t sb = stage_base(s);
        #pragma unroll
        for (int i = 0; i < 2; ++i) {
            int slot = tid + i * 256;
            int r = slot >> 2;
            int c = slot & 3;
            uint32_t so = tile_off(r, c);
            int ga = row0 + r;
            int szA = (ga < Mdim) ? 16 : 0;
            const __nv_bfloat16* pAh = Ahi + (size_t)(szA ? ga : 0) * Kdim + k0 + c * 8;
            const __nv_bfloat16* pAl = Alo + (size_t)(szA ? ga : 0) * Kdim + k0 + c * 8;
            cp_async16(sb + so,        pAh, szA);
            cp_async16(sb + 8192 + so, pAl, szA);
            const __nv_bfloat16* pBh = Bhi + (size_t)(col0 + r) * Kdim + k0 + c * 8;
            const __nv_bfloat16* pBl = Blo + (size_t)(col0 + r) * Kdim + k0 + c * 8;
            cp_async16(sb + 16384 + so, pBh, 16);
            cp_async16(sb + 24576 + so, pBl, 16);
        }
    };

    float acc[4][4][4];
    #pragma unroll
    for (int i = 0; i < 4; ++i)
        #pragma unroll
        for (int j = 0; j < 4; ++j)
            #pragma unroll
            for (int e = 0; e < 4; ++e) acc[i][j][e] = 0.0f;

    const int lrow = lid & 15;
    const int lhi  = lid >> 4;

    const int nck = Kdim >> 5;
    load_stage(0, 0);
    cp_commit();

    for (int ck = 0; ck < nck; ++ck) {
        if (ck + 1 < nck) { load_stage((ck + 1) & 1, (ck + 1) << 5); cp_commit(); }
        if (ck + 1 < nck) cp_wait<1>(); else cp_wait<0>();
        __syncthreads();

        const uint32_t sb = stage_base(ck & 1);
        const uint32_t bAhi = sb, bAlo = sb + 8192;
        const uint32_t bBhi = sb + 16384, bBlo = sb + 24576;

        #pragma unroll
        for (int s = 0; s < 2; ++s) {
            const int cch = 2 * s + lhi;
            uint32_t ah[4][4], al[4][4], bh[2][4], bl[2][4];

            #pragma unroll
            for (int mt = 0; mt < 4; ++mt) {
                int r = wr * 64 + mt * 16 + lrow;
                uint32_t o = tile_off(r, cch);
                ldsm_x4(ah[mt][0], ah[mt][1], ah[mt][2], ah[mt][3], bAhi + o);
            }
            #pragma unroll
            for (int g = 0; g < 2; ++g) {
                int r = wc * 32 + g * 16 + lrow;
                uint32_t o = tile_off(r, cch);
                ldsm_x4(bh[g][0], bh[g][1], bh[g][2], bh[g][3], bBhi + o);
            }
            #pragma unroll
            for (int mt = 0; mt < 4; ++mt)
                #pragma unroll
                for (int nt = 0; nt < 4; ++nt) {
                    uint32_t bb[2] = { bh[nt >> 1][nt & 1], bh[nt >> 1][(nt & 1) + 2] };
                    mma_bf16(acc[mt][nt], ah[mt], bb);
                }
            #pragma unroll
            for (int mt = 0; mt < 4; ++mt) {
                int r = wr * 64 + mt * 16 + lrow;
                uint32_t o = tile_off(r, cch);
                ldsm_x4(al[mt][0], al[mt][1], al[mt][2], al[mt][3], bAlo + o);
            }
            #pragma unroll
            for (int mt = 0; mt < 4; ++mt)
                #pragma unroll
                for (int nt = 0; nt < 4; ++nt) {
                    uint32_t bb[2] = { bh[nt >> 1][nt & 1], bh[nt >> 1][(nt & 1) + 2] };
                    mma_bf16(acc[mt][nt], al[mt], bb);
                }
            #pragma unroll
            for (int g = 0; g < 2; ++g) {
                int r = wc * 32 + g * 16 + lrow;
                uint32_t o = tile_off(r, cch);
                ldsm_x4(bl[g][0], bl[g][1], bl[g][2], bl[g][3], bBlo + o);
            }
            #pragma unroll
            for (int mt = 0; mt < 4; ++mt)
                #pragma unroll
                for (int nt = 0; nt < 4; ++nt) {
                    uint32_t bb[2] = { bl[nt >> 1][nt & 1], bl[nt >> 1][(nt & 1) + 2] };
                    mma_bf16(acc[mt][nt], ah[mt], bb);
                }
        }
        __syncthreads();
    }

    // ---- epilogue ----------------------------------------------------------
    const int g4 = lid >> 2, t4 = lid & 3;
    #pragma unroll
    for (int mt = 0; mt < 4; ++mt) {
        #pragma unroll
        for (int half = 0; half < 2; ++half) {
            int grow = row0 + wr * 64 + mt * 16 + g4 + half * 8;
            if (grow >= Mdim) continue;
            #pragma unroll
            for (int nt = 0; nt < 4; ++nt) {
                int gc = col0 + wc * 32 + nt * 8 + t4 * 2;
                float ox = acc[mt][nt][half * 2 + 0] + bias[gc + 0];
                float oy = acc[mt][nt][half * 2 + 1] + bias[gc + 1];
                if (Chi) {
                    uint32_t h, l;
                    split_pack2(ox, oy, h, l);
                    *reinterpret_cast<uint32_t*>(&Chi[(size_t)grow * Ndim + gc]) = h;
                    *reinterpret_cast<uint32_t*>(&Clo[(size_t)grow * Ndim + gc]) = l;
                } else {
                    float2 o2; o2.x = ox; o2.y = oy;
                    *reinterpret_cast<float2*>(&C[(size_t)grow * Ndim + gc]) = o2;
                }
            }
        }
    }
}

// ---------------------------------------------------------------------------
// Tensor-core flash attention (mma.sync bf16, 3-term split on QK^T and PV).
// Block: 128 thr (4 warps), 64 queries x 10 key tiles of 64. smem 48KB.
// ---------------------------------------------------------------------------
__global__ __launch_bounds__(128) void attn_tc_kernel(
    const __nv_bfloat16* __restrict__ qkvhi,
    const __nv_bfloat16* __restrict__ qkvlo,
    __nv_bfloat16* __restrict__ outhi,
    __nv_bfloat16* __restrict__ outlo)
{
    __shared__ __nv_bfloat16 sQh[64 * 64], sQl[64 * 64];
    __shared__ __nv_bfloat16 sKh[64 * 64], sKl[64 * 64];
    __shared__ __nv_bfloat16 sVh[64 * 64], sVl[64 * 64];

    const int tid = threadIdx.x;
    const int wid = tid >> 5, lid = tid & 31;
    const int q0 = blockIdx.x * 64;
    const int h  = blockIdx.y;
    const int b  = blockIdx.z;

    const uint32_t bQh = smem_u32(sQh), bQl = smem_u32(sQl);
    const uint32_t bKh = smem_u32(sKh), bKl = smem_u32(sKl);
    const uint32_t bVh = smem_u32(sVh), bVl = smem_u32(sVl);

    // global base pointers (row 0 of this (b,h))
    const size_t rb = (size_t)b * S_ * N3_ + h * 64;
    const __nv_bfloat16* pQh = qkvhi + rb;
    const __nv_bfloat16* pQl = qkvlo + rb;
    const __nv_bfloat16* pKh = qkvhi + rb + D_;
    const __nv_bfloat16* pKl = qkvlo + rb + D_;
    const __nv_bfloat16* pVh = qkvhi + rb + 2 * D_;
    const __nv_bfloat16* pVl = qkvlo + rb + 2 * D_;

    // tile loader: 64 rows x 64 bf16, 4 chunks/thread
    auto load_tile = [&](uint32_t sb, const __nv_bfloat16* p, int row_base) {
        #pragma unroll
        for (int i = 0; i < 4; ++i) {
            int slot = tid + (i << 7);
            int r = slot >> 3, c = slot & 7;
            int gr = row_base + r;
            int sz = (gr < S_) ? 16 : 0;
            const __nv_bfloat16* src = p + (size_t)(sz ? gr : 0) * N3_ + c * 8;
            cp_async16(sb + soff(r, c), src, sz);
        }
    };

    // Q tiles (issued once; commit with first K/V group)
    load_tile(bQh, pQh, q0);
    load_tile(bQl, pQl, q0);

    float o[8][4];
    #pragma unroll
    for (int dt = 0; dt < 8; ++dt)
        #pragma unroll
        for (int e = 0; e < 4; ++e) o[dt][e] = 0.0f;
    float m0 = -1e30f, m1 = -1e30f, l0 = 0.0f, l1 = 0.0f;

    const int NT = (S_ + 63) / 64;   // 10
    for (int kt = 0; kt < NT; ++kt) {
        const int kb = kt * 64;
        load_tile(bKh, pKh, kb);
        load_tile(bKl, pKl, kb);
        load_tile(bVh, pVh, kb);
        load_tile(bVl, pVl, kb);
        cp_commit();
        cp_wait<0>();
        __syncthreads();

        // ---- QK^T: sc[nt] over 64 keys -------------------------------------
        float sc[8][4];
        #pragma unroll
        for (int nt = 0; nt < 8; ++nt)
            #pragma unroll
            for (int e = 0; e < 4; ++e) sc[nt][e] = 0.0f;

        #pragma unroll
        for (int s = 0; s < 4; ++s) {
            uint32_t qh[4], ql[4];
            {
                int r = (wid << 4) + (lid & 15);
                int ch = 2 * s + (lid >> 4);
                uint32_t of = soff(r, ch);
                ldsm_x4(qh[0], qh[1], qh[2], qh[3], bQh + of);
                ldsm_x4(ql[0], ql[1], ql[2], ql[3], bQl + of);
            }
            #pragma unroll
            for (int np = 0; np < 4; ++np) {
                int g2 = lid >> 3;
                int r = (np << 4) + ((g2 >> 1) << 3) + (lid & 7);
                int ch = 2 * s + (g2 & 1);
                uint32_t of = soff(r, ch);
                uint32_t kh[4], kl[4];
                ldsm_x4(kh[0], kh[1], kh[2], kh[3], bKh + of);
                ldsm_x4(kl[0], kl[1], kl[2], kl[3], bKl + of);
                uint32_t b0[2] = { kh[0], kh[1] }, b1[2] = { kh[2], kh[3] };
                uint32_t c0[2] = { kl[0], kl[1] }, c1[2] = { kl[2], kl[3] };
                mma_bf16(sc[2 * np],     qh, b0);
                mma_bf16(sc[2 * np],     ql, b0);
                mma_bf16(sc[2 * np],     qh, c0);
                mma_bf16(sc[2 * np + 1], qh, b1);
                mma_bf16(sc[2 * np + 1], ql, b1);
                mma_bf16(sc[2 * np + 1], qh, c1);
            }
        }

        // ---- online softmax (fp32) -----------------------------------------
        #pragma unroll
        for (int nt = 0; nt < 8; ++nt) {
            int c0i = kb + 8 * nt + 2 * (lid & 3);
            bool v0 = c0i < S_, v1 = (c0i + 1) < S_;
            sc[nt][0] = v0 ? sc[nt][0] * SCALE_ : -1e30f;
            sc[nt][1] = v1 ? sc[nt][1] * SCALE_ : -1e30f;
            sc[nt][2] = v0 ? sc[nt][2] * SCALE_ : -1e30f;
            sc[nt][3] = v1 ? sc[nt][3] * SCALE_ : -1e30f;
        }
        float mx0 = -1e30f, mx1 = -1e30f;
        #pragma unroll
        for (int nt = 0; nt < 8; ++nt) {
            mx0 = fmaxf(mx0, fmaxf(sc[nt][0], sc[nt][1]));
            mx1 = fmaxf(mx1, fmaxf(sc[nt][2], sc[nt][3]));
        }
        mx0 = fmaxf(mx0, __shfl_xor_sync(0xffffffffu, mx0, 1));
        mx0 = fmaxf(mx0, __shfl_xor_sync(0xffffffffu, mx0, 2));
        mx1 = fmaxf(mx1, __shfl_xor_sync(0xffffffffu, mx1, 1));
        mx1 = fmaxf(mx1, __shfl_xor_sync(0xffffffffu, mx1, 2));
        float mn0 = fmaxf(m0, mx0), mn1 = fmaxf(m1, mx1);
        float f0 = __expf(m0 - mn0), f1 = __expf(m1 - mn1);
        float s0 = 0.0f, s1 = 0.0f;
        #pragma unroll
        for (int nt = 0; nt < 8; ++nt) {
            sc[nt][0] = __expf(sc[nt][0] - mn0);
            sc[nt][1] = __expf(sc[nt][1] - mn0);
            sc[nt][2] = __expf(sc[nt][2] - mn1);
            sc[nt][3] = __expf(sc[nt][3] - mn1);
            s0 += sc[nt][0] + sc[nt][1];
            s1 += sc[nt][2] + sc[nt][3];
        }
        s0 += __shfl_xor_sync(0xffffffffu, s0, 1);
        s0 += __shfl_xor_sync(0xffffffffu, s0, 2);
        s1 += __shfl_xor_sync(0xffffffffu, s1, 1);
        s1 += __shfl_xor_sync(0xffffffffu, s1, 2);
        l0 = l0 * f0 + s0;
        l1 = l1 * f1 + s1;
        m0 = mn0; m1 = mn1;
        #pragma unroll
        for (int dt = 0; dt < 8; ++dt) {
            o[dt][0] *= f0; o[dt][1] *= f0;
            o[dt][2] *= f1; o[dt][3] *= f1;
        }

        // ---- PV: o += P @ V -------------------------------------------------
        #pragma unroll
        for (int t = 0; t < 4; ++t) {
            uint32_t ph[4], pl[4];
            split_pack2(sc[2 * t][0],     sc[2 * t][1],     ph[0], pl[0]);
            split_pack2(sc[2 * t][2],     sc[2 * t][3],     ph[1], pl[1]);
            split_pack2(sc[2 * t + 1][0], sc[2 * t + 1][1], ph[2], pl[2]);
            split_pack2(sc[2 * t + 1][2], sc[2 * t + 1][3], ph[3], pl[3]);
            #pragma unroll
            for (int dp = 0; dp < 4; ++dp) {
                int g2 = lid >> 3;
                int r = (t << 4) + ((g2 & 1) << 3) + (lid & 7);
                int ch = 2 * dp + (g2 >> 1);
                uint32_t of = soff(r, ch);
                uint32_t vh[4], vl[4];
                ldsm_x4_t(vh[0], vh[1], vh[2], vh[3], bVh + of);
                ldsm_x4_t(vl[0], vl[1], vl[2], vl[3], bVl + of);
                uint32_t b0[2] = { vh[0], vh[1] }, b1[2] = { vh[2], vh[3] };
                uint32_t c0[2] = { vl[0], vl[1] }, c1[2] = { vl[2], vl[3] };
                mma_bf16(o[2 * dp],     ph, b0);
                mma_bf16(o[2 * dp],     pl, b0);
                mma_bf16(o[2 * dp],     ph, c0);
                mma_bf16(o[2 * dp + 1], ph, b1);
                mma_bf16(o[2 * dp + 1], pl, b1);
                mma_bf16(o[2 * dp + 1], ph, c1);
            }
        }
        __syncthreads();   // before next tile's loads overwrite K/V smem
    }

    // ---- epilogue: normalize + write hi/lo bf16 ----------------------------
    const int qa = q0 + (wid << 4) + (lid >> 2);
    const int qb2 = qa + 8;
    const float inv0 = 1.0f / l0, inv1 = 1.0f / l1;
    #pragma unroll
    for (int dt = 0; dt < 8; ++dt) {
        int col = h * 64 + 8 * dt + 2 * (lid & 3);
        if (qa < S_) {
            uint32_t hh, ll;
            split_pack2(o[dt][0] * inv0, o[dt][1] * inv0, hh, ll);
            size_t off = (size_t)(b * S_ + qa) * D_ + col;
            *reinterpret_cast<uint32_t*>(&outhi[off]) = hh;
            *reinterpret_cast<uint32_t*>(&outlo[off]) = ll;
        }
        if (qb2 < S_) {
            uint32_t hh, ll;
            split_pack2(o[dt][2] * inv1, o[dt][3] * inv1, hh, ll);
            size_t off = (size_t)(b * S_ + qb2) * D_ + col;
            *reinterpret_cast<uint32_t*>(&outhi[off]) = hh;
            *reinterpret_cast<uint32_t*>(&outlo[off]) = ll;
        }
    }
}

// ---------------------------------------------------------------------------
extern "C" void kernel_launch(void* const* d_in, const int* in_sizes, int n_in,
                              void* d_out, int out_size)
{
    const float* x     = (const float*)d_in[0];
    const float* w_qkv = (const float*)d_in[1];
    const float* b_qkv = (const float*)d_in[2];
    const float* w_fc  = (const float*)d_in[3];
    const float* b_fc  = (const float*)d_in[4];
    float* out = (float*)d_out;

    __nv_bfloat16 *xhi, *xlo, *qkvh, *qkvl, *atth, *attl, *wqh, *wql, *wfh, *wfl;
    cudaGetSymbolAddress((void**)&xhi,  g_xhi);
    cudaGetSymbolAddress((void**)&xlo,  g_xlo);
    cudaGetSymbolAddress((void**)&qkvh, g_qkvhi);
    cudaGetSymbolAddress((void**)&qkvl, g_qkvlo);
    cudaGetSymbolAddress((void**)&atth, g_atthi);
    cudaGetSymbolAddress((void**)&attl, g_attlo);
    cudaGetSymbolAddress((void**)&wqh,  g_wqhiT);
    cudaGetSymbolAddress((void**)&wql,  g_wqloT);
    cudaGetSymbolAddress((void**)&wfh,  g_wfhiT);
    cudaGetSymbolAddress((void**)&wfl,  g_wfloT);

    static bool attr_set = false;
    if (!attr_set) {
        cudaFuncSetAttribute(gemm_tc_kernel,
                             cudaFuncAttributeMaxDynamicSharedMemorySize,
                             GEMM_SMEM);
        attr_set = true;
    }

    // 0) Precision-split conversions (x + weights)
    {
        int n4 = (M_ * D_) / 4;
        split_kernel<<<(n4 + 255) / 256, 256>>>(x, xhi, xlo, n4);
    }
    wsplit_kernel<<<(N3_ * D_ + 255) / 256, 256>>>(w_qkv, wqh, wql, D_, N3_);
    wsplit_kernel<<<(D_ * D_ + 255) / 256, 256>>>(w_fc, wfh, wfl, D_, D_);

    // 1) QKV projection -> bf16 hi/lo directly (no fp32 round trip)
    gemm_tc_kernel<<<dim3(N3_ / 128, (M_ + 127) / 128), 256, GEMM_SMEM>>>(
        xhi, xlo, wqh, wql, b_qkv, nullptr, qkvh, qkvl, M_, N3_, D_);

    // 2) Tensor-core flash attention -> bf16 hi/lo
    attn_tc_kernel<<<dim3((S_ + 63) / 64, H_, B_), 128>>>(qkvh, qkvl, atth, attl);

    // 3) Output projection -> fp32 d_out
    gemm_tc_kernel<<<dim3(D_ / 128, (M_ + 127) / 128), 256, GEMM_SMEM>>>(
        atth, attl, wfh, wfl, b_fc, out, nullptr, nullptr, M_, D_, D_);
}

// round 12
// speedup vs baseline: 3.0427x; 1.1524x over previous
#include <cuda_runtime.h>
#include <cuda_bf16.h>
#include <math.h>
#include <cstdint>

#define B_   32
#define S_   577
#define D_   768
#define H_   12
#define M_   (B_ * S_)      // 18464
#define N3_  (3 * D_)       // 2304
#define SCALE_ 0.125f       // 1/sqrt(64)

// ---------------- scratch (device globals; no cudaMalloc) -------------------
__device__ __nv_bfloat16 g_xhi[(size_t)M_ * D_];
__device__ __nv_bfloat16 g_xlo[(size_t)M_ * D_];
__device__ __nv_bfloat16 g_qkvhi[(size_t)M_ * N3_];
__device__ __nv_bfloat16 g_qkvlo[(size_t)M_ * N3_];
__device__ __nv_bfloat16 g_atthi[(size_t)M_ * D_];
__device__ __nv_bfloat16 g_attlo[(size_t)M_ * D_];
__device__ __nv_bfloat16 g_wqhiT[(size_t)N3_ * D_];
__device__ __nv_bfloat16 g_wqloT[(size_t)N3_ * D_];
__device__ __nv_bfloat16 g_wfhiT[(size_t)D_ * D_];
__device__ __nv_bfloat16 g_wfloT[(size_t)D_ * D_];

// ---------------- base-ISA PTX helpers --------------------------------------
__device__ __forceinline__ uint32_t smem_u32(const void* p) {
    uint32_t a;
    asm("{ .reg .u64 t; cvta.to.shared.u64 t, %1; cvt.u32.u64 %0, t; }"
        : "=r"(a) : "l"(p));
    return a;
}
__device__ __forceinline__ void cp_async16(uint32_t dst, const void* src, int sz) {
    asm volatile("cp.async.cg.shared.global [%0], [%1], 16, %2;"
                 :: "r"(dst), "l"(src), "r"(sz) : "memory");
}
__device__ __forceinline__ void cp_commit() {
    asm volatile("cp.async.commit_group;" ::: "memory");
}
template <int N>
__device__ __forceinline__ void cp_wait() {
    asm volatile("cp.async.wait_group %0;" :: "n"(N) : "memory");
}
__device__ __forceinline__ void ldsm_x4(uint32_t& r0, uint32_t& r1,
                                        uint32_t& r2, uint32_t& r3, uint32_t a) {
    asm volatile("ldmatrix.sync.aligned.m8n8.x4.shared.b16 {%0,%1,%2,%3}, [%4];"
                 : "=r"(r0), "=r"(r1), "=r"(r2), "=r"(r3) : "r"(a));
}
__device__ __forceinline__ void ldsm_x4_t(uint32_t& r0, uint32_t& r1,
                                          uint32_t& r2, uint32_t& r3, uint32_t a) {
    asm volatile("ldmatrix.sync.aligned.m8n8.x4.trans.shared.b16 {%0,%1,%2,%3}, [%4];"
                 : "=r"(r0), "=r"(r1), "=r"(r2), "=r"(r3) : "r"(a));
}
__device__ __forceinline__ void mma_bf16(float* c, const uint32_t* a,
                                         const uint32_t* b) {
    asm volatile(
        "mma.sync.aligned.m16n8k16.row.col.f32.bf16.bf16.f32 "
        "{%0,%1,%2,%3}, {%4,%5,%6,%7}, {%8,%9}, {%0,%1,%2,%3};"
        : "+f"(c[0]), "+f"(c[1]), "+f"(c[2]), "+f"(c[3])
        : "r"(a[0]), "r"(a[1]), "r"(a[2]), "r"(a[3]), "r"(b[0]), "r"(b[1]));
}

__device__ __forceinline__ void split_pack2(float a, float b,
                                            uint32_t& hi, uint32_t& lo) {
    __nv_bfloat16 ah = __float2bfloat16(a);
    __nv_bfloat16 bh = __float2bfloat16(b);
    __nv_bfloat16 al = __float2bfloat16(a - __bfloat162float(ah));
    __nv_bfloat16 bl = __float2bfloat16(b - __bfloat162float(bh));
    __nv_bfloat162 h2 = __nv_bfloat162(ah, bh);
    __nv_bfloat162 l2 = __nv_bfloat162(al, bl);
    hi = *reinterpret_cast<uint32_t*>(&h2);
    lo = *reinterpret_cast<uint32_t*>(&l2);
}

__device__ __forceinline__ uint32_t tile_off(int r, int c) {
    return (uint32_t)(r * 64 + ((c ^ ((r >> 1) & 3)) << 4));
}
__device__ __forceinline__ uint32_t soff(int r, int c) {
    return (uint32_t)((r << 7) + (((c ^ (r & 7)) & 7) << 4));
}

// ---------------- conversion kernels ---------------------------------------
__global__ void split_kernel(const float* __restrict__ src,
                             __nv_bfloat16* __restrict__ hi,
                             __nv_bfloat16* __restrict__ lo, int n4)
{
    int i = blockIdx.x * blockDim.x + threadIdx.x;
    if (i >= n4) return;
    float4 v = reinterpret_cast<const float4*>(src)[i];
    float xs[4] = {v.x, v.y, v.z, v.w};
    #pragma unroll
    for (int j = 0; j < 4; ++j) {
        __nv_bfloat16 h = __float2bfloat16(xs[j]);
        hi[i * 4 + j] = h;
        lo[i * 4 + j] = __float2bfloat16(xs[j] - __bfloat162float(h));
    }
}

__global__ void wsplit_kernel(const float* __restrict__ w,
                              __nv_bfloat16* __restrict__ hiT,
                              __nv_bfloat16* __restrict__ loT, int K, int N)
{
    int idx = blockIdx.x * blockDim.x + threadIdx.x;
    if (idx >= N * K) return;
    int n = idx / K, k = idx - n * K;
    float x = w[(size_t)k * N + n];
    __nv_bfloat16 h = __float2bfloat16(x);
    hiT[idx] = h;
    loT[idx] = __float2bfloat16(x - __bfloat162float(h));
}

// ---------------------------------------------------------------------------
// Tensor-core GEMM (mma.sync bf16, 3-term split), register-lean mainloop:
// B fragments loaded per k16 step; A fragments loaded per 16-row strip so
// only 8 A regs are live -> fits 128 regs -> 2 CTAs/SM.
// ---------------------------------------------------------------------------
#define STAGE_BYTES 32768
#define GEMM_SMEM   (2 * STAGE_BYTES)

__global__ __launch_bounds__(256, 2) void gemm_tc_kernel(
    const __nv_bfloat16* __restrict__ Ahi, const __nv_bfloat16* __restrict__ Alo,
    const __nv_bfloat16* __restrict__ Bhi, const __nv_bfloat16* __restrict__ Blo,
    const float* __restrict__ bias, float* __restrict__ C,
    __nv_bfloat16* __restrict__ Chi, __nv_bfloat16* __restrict__ Clo,
    int Mdim, int Ndim, int Kdim)
{
    extern __shared__ char smem[];
    const uint32_t sbase = smem_u32(smem);
    const int tid = threadIdx.x;
    const int wid = tid >> 5, lid = tid & 31;
    const int wr = wid >> 2;
    const int wc = wid & 3;
    const int row0 = blockIdx.y * 128, col0 = blockIdx.x * 128;

    auto load_stage = [&](int s, int k0) {
        uint32_t sb = sbase + s * STAGE_BYTES;
        #pragma unroll
        for (int i = 0; i < 2; ++i) {
            int slot = tid + i * 256;
            int r = slot >> 2;
            int c = slot & 3;
            uint32_t so = tile_off(r, c);
            int ga = row0 + r;
            int szA = (ga < Mdim) ? 16 : 0;
            const __nv_bfloat16* pAh = Ahi + (size_t)(szA ? ga : 0) * Kdim + k0 + c * 8;
            const __nv_bfloat16* pAl = Alo + (size_t)(szA ? ga : 0) * Kdim + k0 + c * 8;
            cp_async16(sb + so,        pAh, szA);
            cp_async16(sb + 8192 + so, pAl, szA);
            const __nv_bfloat16* pBh = Bhi + (size_t)(col0 + r) * Kdim + k0 + c * 8;
            const __nv_bfloat16* pBl = Blo + (size_t)(col0 + r) * Kdim + k0 + c * 8;
            cp_async16(sb + 16384 + so, pBh, 16);
            cp_async16(sb + 24576 + so, pBl, 16);
        }
    };

    float acc[4][4][4];
    #pragma unroll
    for (int i = 0; i < 4; ++i)
        #pragma unroll
        for (int j = 0; j < 4; ++j)
            #pragma unroll
            for (int e = 0; e < 4; ++e) acc[i][j][e] = 0.0f;

    const int lrow = lid & 15;
    const int lhi  = lid >> 4;

    const int nck = Kdim >> 5;
    load_stage(0, 0);
    cp_commit();

    for (int ck = 0; ck < nck; ++ck) {
        if (ck + 1 < nck) { load_stage((ck + 1) & 1, (ck + 1) << 5); cp_commit(); }
        if (ck + 1 < nck) cp_wait<1>(); else cp_wait<0>();
        __syncthreads();

        const uint32_t sb = sbase + (ck & 1) * STAGE_BYTES;
        const uint32_t bAhi = sb, bAlo = sb + 8192;
        const uint32_t bBhi = sb + 16384, bBlo = sb + 24576;

        #pragma unroll
        for (int s = 0; s < 2; ++s) {
            const int cch = 2 * s + lhi;
            uint32_t bh[2][4], bl[2][4];
            #pragma unroll
            for (int g = 0; g < 2; ++g) {
                int r = wc * 32 + g * 16 + lrow;
                uint32_t o = tile_off(r, cch);
                ldsm_x4(bh[g][0], bh[g][1], bh[g][2], bh[g][3], bBhi + o);
                ldsm_x4(bl[g][0], bl[g][1], bl[g][2], bl[g][3], bBlo + o);
            }
            #pragma unroll
            for (int mt = 0; mt < 4; ++mt) {
                uint32_t ah[4], al[4];
                int r = wr * 64 + mt * 16 + lrow;
                uint32_t o = tile_off(r, cch);
                ldsm_x4(ah[0], ah[1], ah[2], ah[3], bAhi + o);
                ldsm_x4(al[0], al[1], al[2], al[3], bAlo + o);
                #pragma unroll
                for (int nt = 0; nt < 4; ++nt) {
                    uint32_t bb[2] = { bh[nt >> 1][nt & 1], bh[nt >> 1][(nt & 1) + 2] };
                    mma_bf16(acc[mt][nt], ah, bb);
                }
                #pragma unroll
                for (int nt = 0; nt < 4; ++nt) {
                    uint32_t bb[2] = { bh[nt >> 1][nt & 1], bh[nt >> 1][(nt & 1) + 2] };
                    mma_bf16(acc[mt][nt], al, bb);
                }
                #pragma unroll
                for (int nt = 0; nt < 4; ++nt) {
                    uint32_t bb[2] = { bl[nt >> 1][nt & 1], bl[nt >> 1][(nt & 1) + 2] };
                    mma_bf16(acc[mt][nt], ah, bb);
                }
            }
        }
        __syncthreads();
    }

    // ---- epilogue ----------------------------------------------------------
    const int g4 = lid >> 2, t4 = lid & 3;
    #pragma unroll
    for (int mt = 0; mt < 4; ++mt) {
        #pragma unroll
        for (int half = 0; half < 2; ++half) {
            int grow = row0 + wr * 64 + mt * 16 + g4 + half * 8;
            if (grow >= Mdim) continue;
            #pragma unroll
            for (int nt = 0; nt < 4; ++nt) {
                int gc = col0 + wc * 32 + nt * 8 + t4 * 2;
                float ox = acc[mt][nt][half * 2 + 0] + bias[gc + 0];
                float oy = acc[mt][nt][half * 2 + 1] + bias[gc + 1];
                if (Chi) {
                    uint32_t h, l;
                    split_pack2(ox, oy, h, l);
                    *reinterpret_cast<uint32_t*>(&Chi[(size_t)grow * Ndim + gc]) = h;
                    *reinterpret_cast<uint32_t*>(&Clo[(size_t)grow * Ndim + gc]) = l;
                } else {
                    float2 o2; o2.x = ox; o2.y = oy;
                    *reinterpret_cast<float2*>(&C[(size_t)grow * Ndim + gc]) = o2;
                }
            }
        }
    }
}

// ---------------------------------------------------------------------------
// Tensor-core flash attention (unchanged — passed at 6.3e-6)
// ---------------------------------------------------------------------------
__global__ __launch_bounds__(128) void attn_tc_kernel(
    const __nv_bfloat16* __restrict__ qkvhi,
    const __nv_bfloat16* __restrict__ qkvlo,
    __nv_bfloat16* __restrict__ outhi,
    __nv_bfloat16* __restrict__ outlo)
{
    __shared__ __nv_bfloat16 sQh[64 * 64], sQl[64 * 64];
    __shared__ __nv_bfloat16 sKh[64 * 64], sKl[64 * 64];
    __shared__ __nv_bfloat16 sVh[64 * 64], sVl[64 * 64];

    const int tid = threadIdx.x;
    const int wid = tid >> 5, lid = tid & 31;
    const int q0 = blockIdx.x * 64;
    const int h  = blockIdx.y;
    const int b  = blockIdx.z;

    const uint32_t bQh = smem_u32(sQh), bQl = smem_u32(sQl);
    const uint32_t bKh = smem_u32(sKh), bKl = smem_u32(sKl);
    const uint32_t bVh = smem_u32(sVh), bVl = smem_u32(sVl);

    const size_t rb = (size_t)b * S_ * N3_ + h * 64;
    const __nv_bfloat16* pQh = qkvhi + rb;
    const __nv_bfloat16* pQl = qkvlo + rb;
    const __nv_bfloat16* pKh = qkvhi + rb + D_;
    const __nv_bfloat16* pKl = qkvlo + rb + D_;
    const __nv_bfloat16* pVh = qkvhi + rb + 2 * D_;
    const __nv_bfloat16* pVl = qkvlo + rb + 2 * D_;

    auto load_tile = [&](uint32_t sb, const __nv_bfloat16* p, int row_base) {
        #pragma unroll
        for (int i = 0; i < 4; ++i) {
            int slot = tid + (i << 7);
            int r = slot >> 3, c = slot & 7;
            int gr = row_base + r;
            int sz = (gr < S_) ? 16 : 0;
            const __nv_bfloat16* src = p + (size_t)(sz ? gr : 0) * N3_ + c * 8;
            cp_async16(sb + soff(r, c), src, sz);
        }
    };

    load_tile(bQh, pQh, q0);
    load_tile(bQl, pQl, q0);

    float o[8][4];
    #pragma unroll
    for (int dt = 0; dt < 8; ++dt)
        #pragma unroll
        for (int e = 0; e < 4; ++e) o[dt][e] = 0.0f;
    float m0 = -1e30f, m1 = -1e30f, l0 = 0.0f, l1 = 0.0f;

    const int NT = (S_ + 63) / 64;
    for (int kt = 0; kt < NT; ++kt) {
        const int kb = kt * 64;
        load_tile(bKh, pKh, kb);
        load_tile(bKl, pKl, kb);
        load_tile(bVh, pVh, kb);
        load_tile(bVl, pVl, kb);
        cp_commit();
        cp_wait<0>();
        __syncthreads();

        float sc[8][4];
        #pragma unroll
        for (int nt = 0; nt < 8; ++nt)
            #pragma unroll
            for (int e = 0; e < 4; ++e) sc[nt][e] = 0.0f;

        #pragma unroll
        for (int s = 0; s < 4; ++s) {
            uint32_t qh[4], ql[4];
            {
                int r = (wid << 4) + (lid & 15);
                int ch = 2 * s + (lid >> 4);
                uint32_t of = soff(r, ch);
                ldsm_x4(qh[0], qh[1], qh[2], qh[3], bQh + of);
                ldsm_x4(ql[0], ql[1], ql[2], ql[3], bQl + of);
            }
            #pragma unroll
            for (int np = 0; np < 4; ++np) {
                int g2 = lid >> 3;
                int r = (np << 4) + ((g2 >> 1) << 3) + (lid & 7);
                int ch = 2 * s + (g2 & 1);
                uint32_t of = soff(r, ch);
                uint32_t kh[4], kl[4];
                ldsm_x4(kh[0], kh[1], kh[2], kh[3], bKh + of);
                ldsm_x4(kl[0], kl[1], kl[2], kl[3], bKl + of);
                uint32_t b0[2] = { kh[0], kh[1] }, b1[2] = { kh[2], kh[3] };
                uint32_t c0[2] = { kl[0], kl[1] }, c1[2] = { kl[2], kl[3] };
                mma_bf16(sc[2 * np],     qh, b0);
                mma_bf16(sc[2 * np],     ql, b0);
                mma_bf16(sc[2 * np],     qh, c0);
                mma_bf16(sc[2 * np + 1], qh, b1);
                mma_bf16(sc[2 * np + 1], ql, b1);
                mma_bf16(sc[2 * np + 1], qh, c1);
            }
        }

        #pragma unroll
        for (int nt = 0; nt < 8; ++nt) {
            int c0i = kb + 8 * nt + 2 * (lid & 3);
            bool v0 = c0i < S_, v1 = (c0i + 1) < S_;
            sc[nt][0] = v0 ? sc[nt][0] * SCALE_ : -1e30f;
            sc[nt][1] = v1 ? sc[nt][1] * SCALE_ : -1e30f;
            sc[nt][2] = v0 ? sc[nt][2] * SCALE_ : -1e30f;
            sc[nt][3] = v1 ? sc[nt][3] * SCALE_ : -1e30f;
        }
        float mx0 = -1e30f, mx1 = -1e30f;
        #pragma unroll
        for (int nt = 0; nt < 8; ++nt) {
            mx0 = fmaxf(mx0, fmaxf(sc[nt][0], sc[nt][1]));
            mx1 = fmaxf(mx1, fmaxf(sc[nt][2], sc[nt][3]));
        }
        mx0 = fmaxf(mx0, __shfl_xor_sync(0xffffffffu, mx0, 1));
        mx0 = fmaxf(mx0, __shfl_xor_sync(0xffffffffu, mx0, 2));
        mx1 = fmaxf(mx1, __shfl_xor_sync(0xffffffffu, mx1, 1));
        mx1 = fmaxf(mx1, __shfl_xor_sync(0xffffffffu, mx1, 2));
        float mn0 = fmaxf(m0, mx0), mn1 = fmaxf(m1, mx1);
        float f0 = __expf(m0 - mn0), f1 = __expf(m1 - mn1);
        float s0 = 0.0f, s1 = 0.0f;
        #pragma unroll
        for (int nt = 0; nt < 8; ++nt) {
            sc[nt][0] = __expf(sc[nt][0] - mn0);
            sc[nt][1] = __expf(sc[nt][1] - mn0);
            sc[nt][2] = __expf(sc[nt][2] - mn1);
            sc[nt][3] = __expf(sc[nt][3] - mn1);
            s0 += sc[nt][0] + sc[nt][1];
            s1 += sc[nt][2] + sc[nt][3];
        }
        s0 += __shfl_xor_sync(0xffffffffu, s0, 1);
        s0 += __shfl_xor_sync(0xffffffffu, s0, 2);
        s1 += __shfl_xor_sync(0xffffffffu, s1, 1);
        s1 += __shfl_xor_sync(0xffffffffu, s1, 2);
        l0 = l0 * f0 + s0;
        l1 = l1 * f1 + s1;
        m0 = mn0; m1 = mn1;
        #pragma unroll
        for (int dt = 0; dt < 8; ++dt) {
            o[dt][0] *= f0; o[dt][1] *= f0;
            o[dt][2] *= f1; o[dt][3] *= f1;
        }

        #pragma unroll
        for (int t = 0; t < 4; ++t) {
            uint32_t ph[4], pl[4];
            split_pack2(sc[2 * t][0],     sc[2 * t][1],     ph[0], pl[0]);
            split_pack2(sc[2 * t][2],     sc[2 * t][3],     ph[1], pl[1]);
            split_pack2(sc[2 * t + 1][0], sc[2 * t + 1][1], ph[2], pl[2]);
            split_pack2(sc[2 * t + 1][2], sc[2 * t + 1][3], ph[3], pl[3]);
            #pragma unroll
            for (int dp = 0; dp < 4; ++dp) {
                int g2 = lid >> 3;
                int r = (t << 4) + ((g2 & 1) << 3) + (lid & 7);
                int ch = 2 * dp + (g2 >> 1);
                uint32_t of = soff(r, ch);
                uint32_t vh[4], vl[4];
                ldsm_x4_t(vh[0], vh[1], vh[2], vh[3], bVh + of);
                ldsm_x4_t(vl[0], vl[1], vl[2], vl[3], bVl + of);
                uint32_t b0[2] = { vh[0], vh[1] }, b1[2] = { vh[2], vh[3] };
                uint32_t c0[2] = { vl[0], vl[1] }, c1[2] = { vl[2], vl[3] };
                mma_bf16(o[2 * dp],     ph, b0);
                mma_bf16(o[2 * dp],     pl, b0);
                mma_bf16(o[2 * dp],     ph, c0);
                mma_bf16(o[2 * dp + 1], ph, b1);
                mma_bf16(o[2 * dp + 1], pl, b1);
                mma_bf16(o[2 * dp + 1], ph, c1);
            }
        }
        __syncthreads();
    }

    const int qa = q0 + (wid << 4) + (lid >> 2);
    const int qb2 = qa + 8;
    const float inv0 = 1.0f / l0, inv1 = 1.0f / l1;
    #pragma unroll
    for (int dt = 0; dt < 8; ++dt) {
        int col = h * 64 + 8 * dt + 2 * (lid & 3);
        if (qa < S_) {
            uint32_t hh, ll;
            split_pack2(o[dt][0] * inv0, o[dt][1] * inv0, hh, ll);
            size_t off = (size_t)(b * S_ + qa) * D_ + col;
            *reinterpret_cast<uint32_t*>(&outhi[off]) = hh;
            *reinterpret_cast<uint32_t*>(&outlo[off]) = ll;
        }
        if (qb2 < S_) {
            uint32_t hh, ll;
            split_pack2(o[dt][2] * inv1, o[dt][3] * inv1, hh, ll);
            size_t off = (size_t)(b * S_ + qb2) * D_ + col;
            *reinterpret_cast<uint32_t*>(&outhi[off]) = hh;
            *reinterpret_cast<uint32_t*>(&outlo[off]) = ll;
        }
    }
}

// ---------------------------------------------------------------------------
extern "C" void kernel_launch(void* const* d_in, const int* in_sizes, int n_in,
                              void* d_out, int out_size)
{
    const float* x     = (const float*)d_in[0];
    const float* w_qkv = (const float*)d_in[1];
    const float* b_qkv = (const float*)d_in[2];
    const float* w_fc  = (const float*)d_in[3];
    const float* b_fc  = (const float*)d_in[4];
    float* out = (float*)d_out;

    __nv_bfloat16 *xhi, *xlo, *qkvh, *qkvl, *atth, *attl, *wqh, *wql, *wfh, *wfl;
    cudaGetSymbolAddress((void**)&xhi,  g_xhi);
    cudaGetSymbolAddress((void**)&xlo,  g_xlo);
    cudaGetSymbolAddress((void**)&qkvh, g_qkvhi);
    cudaGetSymbolAddress((void**)&qkvl, g_qkvlo);
    cudaGetSymbolAddress((void**)&atth, g_atthi);
    cudaGetSymbolAddress((void**)&attl, g_attlo);
    cudaGetSymbolAddress((void**)&wqh,  g_wqhiT);
    cudaGetSymbolAddress((void**)&wql,  g_wqloT);
    cudaGetSymbolAddress((void**)&wfh,  g_wfhiT);
    cudaGetSymbolAddress((void**)&wfl,  g_wfloT);

    static bool attr_set = false;
    if (!attr_set) {
        cudaFuncSetAttribute(gemm_tc_kernel,
                             cudaFuncAttributeMaxDynamicSharedMemorySize,
                             GEMM_SMEM);
        attr_set = true;
    }

    {
        int n4 = (M_ * D_) / 4;
        split_kernel<<<(n4 + 255) / 256, 256>>>(x, xhi, xlo, n4);
    }
    wsplit_kernel<<<(N3_ * D_ + 255) / 256, 256>>>(w_qkv, wqh, wql, D_, N3_);
    wsplit_kernel<<<(D_ * D_ + 255) / 256, 256>>>(w_fc, wfh, wfl, D_, D_);

    gemm_tc_kernel<<<dim3(N3_ / 128, (M_ + 127) / 128), 256, GEMM_SMEM>>>(
        xhi, xlo, wqh, wql, b_qkv, nullptr, qkvh, qkvl, M_, N3_, D_);

    attn_tc_kernel<<<dim3((S_ + 63) / 64, H_, B_), 128>>>(qkvh, qkvl, atth, attl);

    gemm_tc_kernel<<<dim3(D_ / 128, (M_ + 127) / 128), 256, GEMM_SMEM>>>(
        atth, attl, wfh, wfl, b_fc, out, nullptr, nullptr, M_, D_, D_);
}

// round 13
// speedup vs baseline: 4.1010x; 1.3478x over previous
#include <cuda_runtime.h>
#include <cuda_fp16.h>
#include <math.h>
#include <cstdint>

#define B_   32
#define S_   577
#define D_   768
#define H_   12
#define M_   (B_ * S_)      // 18464
#define N3_  (3 * D_)       // 2304
#define SCALE_ 0.125f       // 1/sqrt(64)

// ---------------- scratch (device globals; no cudaMalloc) -------------------
__device__ __half g_xhi[(size_t)M_ * D_];
__device__ __half g_xlo[(size_t)M_ * D_];
__device__ __half g_qkvhi[(size_t)M_ * N3_];
__device__ __half g_qkvlo[(size_t)M_ * N3_];
__device__ __half g_atthi[(size_t)M_ * D_];
__device__ __half g_attlo[(size_t)M_ * D_];
__device__ __half g_wqT[(size_t)N3_ * D_];    // w_qkv^T [N,K] fp16
__device__ __half g_wfT[(size_t)D_ * D_];     // w_fc^T  [N,K] fp16

// ---------------- base-ISA PTX helpers --------------------------------------
__device__ __forceinline__ uint32_t smem_u32(const void* p) {
    uint32_t a;
    asm("{ .reg .u64 t; cvta.to.shared.u64 t, %1; cvt.u32.u64 %0, t; }"
        : "=r"(a) : "l"(p));
    return a;
}
__device__ __forceinline__ void cp_async16(uint32_t dst, const void* src, int sz) {
    asm volatile("cp.async.cg.shared.global [%0], [%1], 16, %2;"
                 :: "r"(dst), "l"(src), "r"(sz) : "memory");
}
__device__ __forceinline__ void cp_commit() {
    asm volatile("cp.async.commit_group;" ::: "memory");
}
template <int N>
__device__ __forceinline__ void cp_wait() {
    asm volatile("cp.async.wait_group %0;" :: "n"(N) : "memory");
}
__device__ __forceinline__ void ldsm_x4(uint32_t& r0, uint32_t& r1,
                                        uint32_t& r2, uint32_t& r3, uint32_t a) {
    asm volatile("ldmatrix.sync.aligned.m8n8.x4.shared.b16 {%0,%1,%2,%3}, [%4];"
                 : "=r"(r0), "=r"(r1), "=r"(r2), "=r"(r3) : "r"(a));
}
__device__ __forceinline__ void ldsm_x4_t(uint32_t& r0, uint32_t& r1,
                                          uint32_t& r2, uint32_t& r3, uint32_t a) {
    asm volatile("ldmatrix.sync.aligned.m8n8.x4.trans.shared.b16 {%0,%1,%2,%3}, [%4];"
                 : "=r"(r0), "=r"(r1), "=r"(r2), "=r"(r3) : "r"(a));
}
__device__ __forceinline__ void mma_f16(float* c, const uint32_t* a,
                                        const uint32_t* b) {
    asm volatile(
        "mma.sync.aligned.m16n8k16.row.col.f32.f16.f16.f32 "
        "{%0,%1,%2,%3}, {%4,%5,%6,%7}, {%8,%9}, {%0,%1,%2,%3};"
        : "+f"(c[0]), "+f"(c[1]), "+f"(c[2]), "+f"(c[3])
        : "r"(a[0]), "r"(a[1]), "r"(a[2]), "r"(a[3]), "r"(b[0]), "r"(b[1]));
}

// split fp32 pair -> packed fp16x2 hi + residual lo
__device__ __forceinline__ void split_pack2h(float a, float b,
                                             uint32_t& hi, uint32_t& lo) {
    __half ah = __float2half_rn(a);
    __half bh = __float2half_rn(b);
    __half al = __float2half_rn(a - __half2float(ah));
    __half bl = __float2half_rn(b - __half2float(bh));
    __half2 h2 = __halves2half2(ah, bh);
    __half2 l2 = __halves2half2(al, bl);
    hi = *reinterpret_cast<uint32_t*>(&h2);
    lo = *reinterpret_cast<uint32_t*>(&l2);
}

__device__ __forceinline__ uint32_t tile_off(int r, int c) {
    return (uint32_t)(r * 64 + ((c ^ ((r >> 1) & 3)) << 4));
}
__device__ __forceinline__ uint32_t soff(int r, int c) {
    return (uint32_t)((r << 7) + (((c ^ (r & 7)) & 7) << 4));
}

// ---------------- conversion kernels ---------------------------------------
__global__ void split_kernel(const float* __restrict__ src,
                             __half* __restrict__ hi,
                             __half* __restrict__ lo, int n4)
{
    int i = blockIdx.x * blockDim.x + threadIdx.x;
    if (i >= n4) return;
    float4 v = reinterpret_cast<const float4*>(src)[i];
    float xs[4] = {v.x, v.y, v.z, v.w};
    #pragma unroll
    for (int j = 0; j < 4; ++j) {
        __half h = __float2half_rn(xs[j]);
        hi[i * 4 + j] = h;
        lo[i * 4 + j] = __float2half_rn(xs[j] - __half2float(h));
    }
}

// w [K,N] fp32 -> wT [N,K] fp16 (single precision term; weights are the
// unsplit right operand)
__global__ void wconv_kernel(const float* __restrict__ w,
                             __half* __restrict__ wT, int K, int N)
{
    int idx = blockIdx.x * blockDim.x + threadIdx.x;
    if (idx >= N * K) return;
    int n = idx / K, k = idx - n * K;
    wT[idx] = __float2half_rn(w[(size_t)k * N + n]);
}

// ---------------------------------------------------------------------------
// Tensor-core GEMM (mma.sync fp16, 2-term: Ah*B + Al*B):
//   C = (Ahi+Alo)[M,K] @ B[N,K]^T + bias
// Output: fp32 C (Chi==null) or fp16 hi/lo pair.
// ---------------------------------------------------------------------------
#define STAGE_BYTES 24576           // Ah(8K) + Al(8K) + B(8K)
#define GEMM_SMEM   (2 * STAGE_BYTES)

__global__ __launch_bounds__(256, 2) void gemm_tc_kernel(
    const __half* __restrict__ Ahi, const __half* __restrict__ Alo,
    const __half* __restrict__ Bm,
    const float* __restrict__ bias, float* __restrict__ C,
    __half* __restrict__ Chi, __half* __restrict__ Clo,
    int Mdim, int Ndim, int Kdim)
{
    extern __shared__ char smem[];
    const uint32_t sbase = smem_u32(smem);
    const int tid = threadIdx.x;
    const int wid = tid >> 5, lid = tid & 31;
    const int wr = wid >> 2;
    const int wc = wid & 3;
    const int row0 = blockIdx.y * 128, col0 = blockIdx.x * 128;

    auto load_stage = [&](int s, int k0) {
        uint32_t sb = sbase + s * STAGE_BYTES;
        #pragma unroll
        for (int i = 0; i < 2; ++i) {
            int slot = tid + i * 256;
            int r = slot >> 2;
            int c = slot & 3;
            uint32_t so = tile_off(r, c);
            int ga = row0 + r;
            int szA = (ga < Mdim) ? 16 : 0;
            const __half* pAh = Ahi + (size_t)(szA ? ga : 0) * Kdim + k0 + c * 8;
            const __half* pAl = Alo + (size_t)(szA ? ga : 0) * Kdim + k0 + c * 8;
            cp_async16(sb + so,        pAh, szA);
            cp_async16(sb + 8192 + so, pAl, szA);
            const __half* pB = Bm + (size_t)(col0 + r) * Kdim + k0 + c * 8;
            cp_async16(sb + 16384 + so, pB, 16);
        }
    };

    float acc[4][4][4];
    #pragma unroll
    for (int i = 0; i < 4; ++i)
        #pragma unroll
        for (int j = 0; j < 4; ++j)
            #pragma unroll
            for (int e = 0; e < 4; ++e) acc[i][j][e] = 0.0f;

    const int lrow = lid & 15;
    const int lhi  = lid >> 4;

    const int nck = Kdim >> 5;
    load_stage(0, 0);
    cp_commit();

    for (int ck = 0; ck < nck; ++ck) {
        if (ck + 1 < nck) { load_stage((ck + 1) & 1, (ck + 1) << 5); cp_commit(); }
        if (ck + 1 < nck) cp_wait<1>(); else cp_wait<0>();
        __syncthreads();

        const uint32_t sb = sbase + (ck & 1) * STAGE_BYTES;
        const uint32_t bAhi = sb, bAlo = sb + 8192, bB = sb + 16384;

        #pragma unroll
        for (int s = 0; s < 2; ++s) {
            const int cch = 2 * s + lhi;
            uint32_t bh[2][4];
            #pragma unroll
            for (int g = 0; g < 2; ++g) {
                int r = wc * 32 + g * 16 + lrow;
                uint32_t o = tile_off(r, cch);
                ldsm_x4(bh[g][0], bh[g][1], bh[g][2], bh[g][3], bB + o);
            }
            #pragma unroll
            for (int mt = 0; mt < 4; ++mt) {
                uint32_t ah[4], al[4];
                int r = wr * 64 + mt * 16 + lrow;
                uint32_t o = tile_off(r, cch);
                ldsm_x4(ah[0], ah[1], ah[2], ah[3], bAhi + o);
                ldsm_x4(al[0], al[1], al[2], al[3], bAlo + o);
                #pragma unroll
                for (int nt = 0; nt < 4; ++nt) {
                    uint32_t bb[2] = { bh[nt >> 1][nt & 1], bh[nt >> 1][(nt & 1) + 2] };
                    mma_f16(acc[mt][nt], ah, bb);
                }
                #pragma unroll
                for (int nt = 0; nt < 4; ++nt) {
                    uint32_t bb[2] = { bh[nt >> 1][nt & 1], bh[nt >> 1][(nt & 1) + 2] };
                    mma_f16(acc[mt][nt], al, bb);
                }
            }
        }
        __syncthreads();
    }

    // ---- epilogue ----------------------------------------------------------
    const int g4 = lid >> 2, t4 = lid & 3;
    #pragma unroll
    for (int mt = 0; mt < 4; ++mt) {
        #pragma unroll
        for (int half = 0; half < 2; ++half) {
            int grow = row0 + wr * 64 + mt * 16 + g4 + half * 8;
            if (grow >= Mdim) continue;
            #pragma unroll
            for (int nt = 0; nt < 4; ++nt) {
                int gc = col0 + wc * 32 + nt * 8 + t4 * 2;
                float ox = acc[mt][nt][half * 2 + 0] + bias[gc + 0];
                float oy = acc[mt][nt][half * 2 + 1] + bias[gc + 1];
                if (Chi) {
                    uint32_t h, l;
                    split_pack2h(ox, oy, h, l);
                    *reinterpret_cast<uint32_t*>(&Chi[(size_t)grow * Ndim + gc]) = h;
                    *reinterpret_cast<uint32_t*>(&Clo[(size_t)grow * Ndim + gc]) = l;
                } else {
                    float2 o2; o2.x = ox; o2.y = oy;
                    *reinterpret_cast<float2*>(&C[(size_t)grow * Ndim + gc]) = o2;
                }
            }
        }
    }
}

// ---------------------------------------------------------------------------
// Tensor-core flash attention (fp16, 2-term: Q split, K/V single).
// Block: 128 thr (4 warps), 64 queries x 10 key tiles. smem 32KB.
// ---------------------------------------------------------------------------
__global__ __launch_bounds__(128) void attn_tc_kernel(
    const __half* __restrict__ qkvhi,
    const __half* __restrict__ qkvlo,
    __half* __restrict__ outhi,
    __half* __restrict__ outlo)
{
    __shared__ __half sQh[64 * 64], sQl[64 * 64];
    __shared__ __half sKh[64 * 64], sVh[64 * 64];

    const int tid = threadIdx.x;
    const int wid = tid >> 5, lid = tid & 31;
    const int q0 = blockIdx.x * 64;
    const int h  = blockIdx.y;
    const int b  = blockIdx.z;

    const uint32_t bQh = smem_u32(sQh), bQl = smem_u32(sQl);
    const uint32_t bKh = smem_u32(sKh), bVh = smem_u32(sVh);

    const size_t rb = (size_t)b * S_ * N3_ + h * 64;
    const __half* pQh = qkvhi + rb;
    const __half* pQl = qkvlo + rb;
    const __half* pKh = qkvhi + rb + D_;
    const __half* pVh = qkvhi + rb + 2 * D_;

    auto load_tile = [&](uint32_t sb, const __half* p, int row_base) {
        #pragma unroll
        for (int i = 0; i < 4; ++i) {
            int slot = tid + (i << 7);
            int r = slot >> 3, c = slot & 7;
            int gr = row_base + r;
            int sz = (gr < S_) ? 16 : 0;
            const __half* src = p + (size_t)(sz ? gr : 0) * N3_ + c * 8;
            cp_async16(sb + soff(r, c), src, sz);
        }
    };

    load_tile(bQh, pQh, q0);
    load_tile(bQl, pQl, q0);

    float o[8][4];
    #pragma unroll
    for (int dt = 0; dt < 8; ++dt)
        #pragma unroll
        for (int e = 0; e < 4; ++e) o[dt][e] = 0.0f;
    float m0 = -1e30f, m1 = -1e30f, l0 = 0.0f, l1 = 0.0f;

    const int NT = (S_ + 63) / 64;
    for (int kt = 0; kt < NT; ++kt) {
        const int kb = kt * 64;
        load_tile(bKh, pKh, kb);
        load_tile(bVh, pVh, kb);
        cp_commit();
        cp_wait<0>();
        __syncthreads();

        float sc[8][4];
        #pragma unroll
        for (int nt = 0; nt < 8; ++nt)
            #pragma unroll
            for (int e = 0; e < 4; ++e) sc[nt][e] = 0.0f;

        #pragma unroll
        for (int s = 0; s < 4; ++s) {
            uint32_t qh[4], ql[4];
            {
                int r = (wid << 4) + (lid & 15);
                int ch = 2 * s + (lid >> 4);
                uint32_t of = soff(r, ch);
                ldsm_x4(qh[0], qh[1], qh[2], qh[3], bQh + of);
                ldsm_x4(ql[0], ql[1], ql[2], ql[3], bQl + of);
            }
            #pragma unroll
            for (int np = 0; np < 4; ++np) {
                int g2 = lid >> 3;
                int r = (np << 4) + ((g2 >> 1) << 3) + (lid & 7);
                int ch = 2 * s + (g2 & 1);
                uint32_t of = soff(r, ch);
                uint32_t kh[4];
                ldsm_x4(kh[0], kh[1], kh[2], kh[3], bKh + of);
                uint32_t b0[2] = { kh[0], kh[1] }, b1[2] = { kh[2], kh[3] };
                mma_f16(sc[2 * np],     qh, b0);
                mma_f16(sc[2 * np],     ql, b0);
                mma_f16(sc[2 * np + 1], qh, b1);
                mma_f16(sc[2 * np + 1], ql, b1);
            }
        }

        #pragma unroll
        for (int nt = 0; nt < 8; ++nt) {
            int c0i = kb + 8 * nt + 2 * (lid & 3);
            bool v0 = c0i < S_, v1 = (c0i + 1) < S_;
            sc[nt][0] = v0 ? sc[nt][0] * SCALE_ : -1e30f;
            sc[nt][1] = v1 ? sc[nt][1] * SCALE_ : -1e30f;
            sc[nt][2] = v0 ? sc[nt][2] * SCALE_ : -1e30f;
            sc[nt][3] = v1 ? sc[nt][3] * SCALE_ : -1e30f;
        }
        float mx0 = -1e30f, mx1 = -1e30f;
        #pragma unroll
        for (int nt = 0; nt < 8; ++nt) {
            mx0 = fmaxf(mx0, fmaxf(sc[nt][0], sc[nt][1]));
            mx1 = fmaxf(mx1, fmaxf(sc[nt][2], sc[nt][3]));
        }
        mx0 = fmaxf(mx0, __shfl_xor_sync(0xffffffffu, mx0, 1));
        mx0 = fmaxf(mx0, __shfl_xor_sync(0xffffffffu, mx0, 2));
        mx1 = fmaxf(mx1, __shfl_xor_sync(0xffffffffu, mx1, 1));
        mx1 = fmaxf(mx1, __shfl_xor_sync(0xffffffffu, mx1, 2));
        float mn0 = fmaxf(m0, mx0), mn1 = fmaxf(m1, mx1);
        float f0 = __expf(m0 - mn0), f1 = __expf(m1 - mn1);
        float s0 = 0.0f, s1 = 0.0f;
        #pragma unroll
        for (int nt = 0; nt < 8; ++nt) {
            sc[nt][0] = __expf(sc[nt][0] - mn0);
            sc[nt][1] = __expf(sc[nt][1] - mn0);
            sc[nt][2] = __expf(sc[nt][2] - mn1);
            sc[nt][3] = __expf(sc[nt][3] - mn1);
            s0 += sc[nt][0] + sc[nt][1];
            s1 += sc[nt][2] + sc[nt][3];
        }
        s0 += __shfl_xor_sync(0xffffffffu, s0, 1);
        s0 += __shfl_xor_sync(0xffffffffu, s0, 2);
        s1 += __shfl_xor_sync(0xffffffffu, s1, 1);
        s1 += __shfl_xor_sync(0xffffffffu, s1, 2);
        l0 = l0 * f0 + s0;
        l1 = l1 * f1 + s1;
        m0 = mn0; m1 = mn1;
        #pragma unroll
        for (int dt = 0; dt < 8; ++dt) {
            o[dt][0] *= f0; o[dt][1] *= f0;
            o[dt][2] *= f1; o[dt][3] *= f1;
        }

        #pragma unroll
        for (int t = 0; t < 4; ++t) {
            uint32_t ph[4], pl[4];
            split_pack2h(sc[2 * t][0],     sc[2 * t][1],     ph[0], pl[0]);
            split_pack2h(sc[2 * t][2],     sc[2 * t][3],     ph[1], pl[1]);
            split_pack2h(sc[2 * t + 1][0], sc[2 * t + 1][1], ph[2], pl[2]);
            split_pack2h(sc[2 * t + 1][2], sc[2 * t + 1][3], ph[3], pl[3]);
            #pragma unroll
            for (int dp = 0; dp < 4; ++dp) {
                int g2 = lid >> 3;
                int r = (t << 4) + ((g2 & 1) << 3) + (lid & 7);
                int ch = 2 * dp + (g2 >> 1);
                uint32_t of = soff(r, ch);
                uint32_t vh[4];
                ldsm_x4_t(vh[0], vh[1], vh[2], vh[3], bVh + of);
                uint32_t b0[2] = { vh[0], vh[1] }, b1[2] = { vh[2], vh[3] };
                mma_f16(o[2 * dp],     ph, b0);
                mma_f16(o[2 * dp],     pl, b0);
                mma_f16(o[2 * dp + 1], ph, b1);
                mma_f16(o[2 * dp + 1], pl, b1);
            }
        }
        __syncthreads();
    }

    const int qa = q0 + (wid << 4) + (lid >> 2);
    const int qb2 = qa + 8;
    const float inv0 = 1.0f / l0, inv1 = 1.0f / l1;
    #pragma unroll
    for (int dt = 0; dt < 8; ++dt) {
        int col = h * 64 + 8 * dt + 2 * (lid & 3);
        if (qa < S_) {
            uint32_t hh, ll;
            split_pack2h(o[dt][0] * inv0, o[dt][1] * inv0, hh, ll);
            size_t off = (size_t)(b * S_ + qa) * D_ + col;
            *reinterpret_cast<uint32_t*>(&outhi[off]) = hh;
            *reinterpret_cast<uint32_t*>(&outlo[off]) = ll;
        }
        if (qb2 < S_) {
            uint32_t hh, ll;
            split_pack2h(o[dt][2] * inv1, o[dt][3] * inv1, hh, ll);
            size_t off = (size_t)(b * S_ + qb2) * D_ + col;
            *reinterpret_cast<uint32_t*>(&outhi[off]) = hh;
            *reinterpret_cast<uint32_t*>(&outlo[off]) = ll;
        }
    }
}

// ---------------------------------------------------------------------------
extern "C" void kernel_launch(void* const* d_in, const int* in_sizes, int n_in,
                              void* d_out, int out_size)
{
    const float* x     = (const float*)d_in[0];
    const float* w_qkv = (const float*)d_in[1];
    const float* b_qkv = (const float*)d_in[2];
    const float* w_fc  = (const float*)d_in[3];
    const float* b_fc  = (const float*)d_in[4];
    float* out = (float*)d_out;

    __half *xhi, *xlo, *qkvh, *qkvl, *atth, *attl, *wq, *wf;
    cudaGetSymbolAddress((void**)&xhi,  g_xhi);
    cudaGetSymbolAddress((void**)&xlo,  g_xlo);
    cudaGetSymbolAddress((void**)&qkvh, g_qkvhi);
    cudaGetSymbolAddress((void**)&qkvl, g_qkvlo);
    cudaGetSymbolAddress((void**)&atth, g_atthi);
    cudaGetSymbolAddress((void**)&attl, g_attlo);
    cudaGetSymbolAddress((void**)&wq,   g_wqT);
    cudaGetSymbolAddress((void**)&wf,   g_wfT);

    static bool attr_set = false;
    if (!attr_set) {
        cudaFuncSetAttribute(gemm_tc_kernel,
                             cudaFuncAttributeMaxDynamicSharedMemorySize,
                             GEMM_SMEM);
        attr_set = true;
    }

    {
        int n4 = (M_ * D_) / 4;
        split_kernel<<<(n4 + 255) / 256, 256>>>(x, xhi, xlo, n4);
    }
    wconv_kernel<<<(N3_ * D_ + 255) / 256, 256>>>(w_qkv, wq, D_, N3_);
    wconv_kernel<<<(D_ * D_ + 255) / 256, 256>>>(w_fc, wf, D_, D_);

    // 1) QKV projection -> fp16 hi/lo
    gemm_tc_kernel<<<dim3(N3_ / 128, (M_ + 127) / 128), 256, GEMM_SMEM>>>(
        xhi, xlo, wq, b_qkv, nullptr, qkvh, qkvl, M_, N3_, D_);

    // 2) Tensor-core flash attention -> fp16 hi/lo
    attn_tc_kernel<<<dim3((S_ + 63) / 64, H_, B_), 128>>>(qkvh, qkvl, atth, attl);

    // 3) Output projection -> fp32 d_out
    gemm_tc_kernel<<<dim3(D_ / 128, (M_ + 127) / 128), 256, GEMM_SMEM>>>(
        atth, attl, wf, b_fc, out, nullptr, nullptr, M_, D_, D_);
}

// round 14
// speedup vs baseline: 4.1655x; 1.0157x over previous
#include <cuda_runtime.h>
#include <cuda_fp16.h>
#include <math.h>
#include <cstdint>

#define B_   32
#define S_   577
#define D_   768
#define H_   12
#define M_   (B_ * S_)      // 18464
#define N3_  (3 * D_)       // 2304
#define SCALE_ 0.125f       // 1/sqrt(64)

// ---------------- scratch (device globals; no cudaMalloc) -------------------
__device__ __half g_xhi[(size_t)M_ * D_];
__device__ __half g_xlo[(size_t)M_ * D_];
__device__ __half g_qkvhi[(size_t)M_ * N3_];
__device__ __half g_qkvlo[(size_t)M_ * N3_];
__device__ __half g_atthi[(size_t)M_ * D_];
__device__ __half g_attlo[(size_t)M_ * D_];
__device__ __half g_wqT[(size_t)N3_ * D_];    // w_qkv^T [N,K] fp16
__device__ __half g_wfT[(size_t)D_ * D_];     // w_fc^T  [N,K] fp16

// ---------------- base-ISA PTX helpers --------------------------------------
__device__ __forceinline__ uint32_t smem_u32(const void* p) {
    uint32_t a;
    asm("{ .reg .u64 t; cvta.to.shared.u64 t, %1; cvt.u32.u64 %0, t; }"
        : "=r"(a) : "l"(p));
    return a;
}
__device__ __forceinline__ void cp_async16(uint32_t dst, const void* src, int sz) {
    asm volatile("cp.async.cg.shared.global [%0], [%1], 16, %2;"
                 :: "r"(dst), "l"(src), "r"(sz) : "memory");
}
__device__ __forceinline__ void cp_commit() {
    asm volatile("cp.async.commit_group;" ::: "memory");
}
template <int N>
__device__ __forceinline__ void cp_wait() {
    asm volatile("cp.async.wait_group %0;" :: "n"(N) : "memory");
}
__device__ __forceinline__ void ldsm_x4(uint32_t& r0, uint32_t& r1,
                                        uint32_t& r2, uint32_t& r3, uint32_t a) {
    asm volatile("ldmatrix.sync.aligned.m8n8.x4.shared.b16 {%0,%1,%2,%3}, [%4];"
                 : "=r"(r0), "=r"(r1), "=r"(r2), "=r"(r3) : "r"(a));
}
__device__ __forceinline__ void ldsm_x4_t(uint32_t& r0, uint32_t& r1,
                                          uint32_t& r2, uint32_t& r3, uint32_t a) {
    asm volatile("ldmatrix.sync.aligned.m8n8.x4.trans.shared.b16 {%0,%1,%2,%3}, [%4];"
                 : "=r"(r0), "=r"(r1), "=r"(r2), "=r"(r3) : "r"(a));
}
__device__ __forceinline__ void mma_f16(float* c, const uint32_t* a,
                                        const uint32_t* b) {
    asm volatile(
        "mma.sync.aligned.m16n8k16.row.col.f32.f16.f16.f32 "
        "{%0,%1,%2,%3}, {%4,%5,%6,%7}, {%8,%9}, {%0,%1,%2,%3};"
        : "+f"(c[0]), "+f"(c[1]), "+f"(c[2]), "+f"(c[3])
        : "r"(a[0]), "r"(a[1]), "r"(a[2]), "r"(a[3]), "r"(b[0]), "r"(b[1]));
}

__device__ __forceinline__ void split_pack2h(float a, float b,
                                             uint32_t& hi, uint32_t& lo) {
    __half ah = __float2half_rn(a);
    __half bh = __float2half_rn(b);
    __half al = __float2half_rn(a - __half2float(ah));
    __half bl = __float2half_rn(b - __half2float(bh));
    __half2 h2 = __halves2half2(ah, bh);
    __half2 l2 = __halves2half2(al, bl);
    hi = *reinterpret_cast<uint32_t*>(&h2);
    lo = *reinterpret_cast<uint32_t*>(&l2);
}

__device__ __forceinline__ uint32_t tile_off(int r, int c) {
    return (uint32_t)(r * 64 + ((c ^ ((r >> 1) & 3)) << 4));
}
__device__ __forceinline__ uint32_t soff(int r, int c) {
    return (uint32_t)((r << 7) + (((c ^ (r & 7)) & 7) << 4));
}

// ---------------- conversion kernels ---------------------------------------
__global__ void split_kernel(const float* __restrict__ src,
                             __half* __restrict__ hi,
                             __half* __restrict__ lo, int n4)
{
    int i = blockIdx.x * blockDim.x + threadIdx.x;
    if (i >= n4) return;
    float4 v = reinterpret_cast<const float4*>(src)[i];
    float xs[4] = {v.x, v.y, v.z, v.w};
    #pragma unroll
    for (int j = 0; j < 4; ++j) {
        __half h = __float2half_rn(xs[j]);
        hi[i * 4 + j] = h;
        lo[i * 4 + j] = __float2half_rn(xs[j] - __half2float(h));
    }
}

__global__ void wconv_kernel(const float* __restrict__ w,
                             __half* __restrict__ wT, int K, int N)
{
    int idx = blockIdx.x * blockDim.x + threadIdx.x;
    if (idx >= N * K) return;
    int n = idx / K, k = idx - n * K;
    wT[idx] = __float2half_rn(w[(size_t)k * N + n]);
}

// ---------------------------------------------------------------------------
// Tensor-core GEMM (mma.sync fp16, 2-term: Ah*B + Al*B), 3-stage cp.async
// ring with ONE barrier per chunk (load for ck+2 issued after barrier at ck;
// that stage was last read at ck-1, which all threads finished pre-barrier).
// ---------------------------------------------------------------------------
#define STAGE_BYTES 24576           // Ah(8K) + Al(8K) + B(8K)
#define NSTAGE      3
#define GEMM_SMEM   (NSTAGE * STAGE_BYTES)

__global__ __launch_bounds__(256, 2) void gemm_tc_kernel(
    const __half* __restrict__ Ahi, const __half* __restrict__ Alo,
    const __half* __restrict__ Bm,
    const float* __restrict__ bias, float* __restrict__ C,
    __half* __restrict__ Chi, __half* __restrict__ Clo,
    int Mdim, int Ndim, int Kdim)
{
    extern __shared__ char smem[];
    const uint32_t sbase = smem_u32(smem);
    const int tid = threadIdx.x;
    const int wid = tid >> 5, lid = tid & 31;
    const int wr = wid >> 2;
    const int wc = wid & 3;
    const int row0 = blockIdx.y * 128, col0 = blockIdx.x * 128;

    auto load_stage = [&](int s, int k0) {
        uint32_t sb = sbase + s * STAGE_BYTES;
        #pragma unroll
        for (int i = 0; i < 2; ++i) {
            int slot = tid + i * 256;
            int r = slot >> 2;
            int c = slot & 3;
            uint32_t so = tile_off(r, c);
            int ga = row0 + r;
            int szA = (ga < Mdim) ? 16 : 0;
            const __half* pAh = Ahi + (size_t)(szA ? ga : 0) * Kdim + k0 + c * 8;
            const __half* pAl = Alo + (size_t)(szA ? ga : 0) * Kdim + k0 + c * 8;
            cp_async16(sb + so,        pAh, szA);
            cp_async16(sb + 8192 + so, pAl, szA);
            const __half* pB = Bm + (size_t)(col0 + r) * Kdim + k0 + c * 8;
            cp_async16(sb + 16384 + so, pB, 16);
        }
        cp_commit();
    };

    float acc[4][4][4];
    #pragma unroll
    for (int i = 0; i < 4; ++i)
        #pragma unroll
        for (int j = 0; j < 4; ++j)
            #pragma unroll
            for (int e = 0; e < 4; ++e) acc[i][j][e] = 0.0f;

    const int lrow = lid & 15;
    const int lhi  = lid >> 4;

    const int nck = Kdim >> 5;
    load_stage(0, 0);
    load_stage(1, 32);

    int stage = 0;
    for (int ck = 0; ck < nck; ++ck) {
        if (ck + 1 < nck) cp_wait<1>(); else cp_wait<0>();
        __syncthreads();
        if (ck + 2 < nck) {
            int s2 = stage + 2; if (s2 >= NSTAGE) s2 -= NSTAGE;
            load_stage(s2, (ck + 2) << 5);
        }

        const uint32_t sb = sbase + stage * STAGE_BYTES;
        const uint32_t bAhi = sb, bAlo = sb + 8192, bB = sb + 16384;

        #pragma unroll
        for (int s = 0; s < 2; ++s) {
            const int cch = 2 * s + lhi;
            uint32_t bh[2][4];
            #pragma unroll
            for (int g = 0; g < 2; ++g) {
                int r = wc * 32 + g * 16 + lrow;
                uint32_t o = tile_off(r, cch);
                ldsm_x4(bh[g][0], bh[g][1], bh[g][2], bh[g][3], bB + o);
            }
            #pragma unroll
            for (int mt = 0; mt < 4; ++mt) {
                uint32_t ah[4], al[4];
                int r = wr * 64 + mt * 16 + lrow;
                uint32_t o = tile_off(r, cch);
                ldsm_x4(ah[0], ah[1], ah[2], ah[3], bAhi + o);
                ldsm_x4(al[0], al[1], al[2], al[3], bAlo + o);
                #pragma unroll
                for (int nt = 0; nt < 4; ++nt) {
                    uint32_t bb[2] = { bh[nt >> 1][nt & 1], bh[nt >> 1][(nt & 1) + 2] };
                    mma_f16(acc[mt][nt], ah, bb);
                }
                #pragma unroll
                for (int nt = 0; nt < 4; ++nt) {
                    uint32_t bb[2] = { bh[nt >> 1][nt & 1], bh[nt >> 1][(nt & 1) + 2] };
                    mma_f16(acc[mt][nt], al, bb);
                }
            }
        }
        if (++stage >= NSTAGE) stage = 0;
    }

    // ---- epilogue ----------------------------------------------------------
    const int g4 = lid >> 2, t4 = lid & 3;
    #pragma unroll
    for (int mt = 0; mt < 4; ++mt) {
        #pragma unroll
        for (int half = 0; half < 2; ++half) {
            int grow = row0 + wr * 64 + mt * 16 + g4 + half * 8;
            if (grow >= Mdim) continue;
            #pragma unroll
            for (int nt = 0; nt < 4; ++nt) {
                int gc = col0 + wc * 32 + nt * 8 + t4 * 2;
                float ox = acc[mt][nt][half * 2 + 0] + bias[gc + 0];
                float oy = acc[mt][nt][half * 2 + 1] + bias[gc + 1];
                if (Chi) {
                    uint32_t h, l;
                    split_pack2h(ox, oy, h, l);
                    *reinterpret_cast<uint32_t*>(&Chi[(size_t)grow * Ndim + gc]) = h;
                    *reinterpret_cast<uint32_t*>(&Clo[(size_t)grow * Ndim + gc]) = l;
                } else {
                    float2 o2; o2.x = ox; o2.y = oy;
                    *reinterpret_cast<float2*>(&C[(size_t)grow * Ndim + gc]) = o2;
                }
            }
        }
    }
}

// ---------------------------------------------------------------------------
// Tensor-core flash attention (fp16, 2-term: Q split, K/V single). Unchanged.
// ---------------------------------------------------------------------------
__global__ __launch_bounds__(128) void attn_tc_kernel(
    const __half* __restrict__ qkvhi,
    const __half* __restrict__ qkvlo,
    __half* __restrict__ outhi,
    __half* __restrict__ outlo)
{
    __shared__ __half sQh[64 * 64], sQl[64 * 64];
    __shared__ __half sKh[64 * 64], sVh[64 * 64];

    const int tid = threadIdx.x;
    const int wid = tid >> 5, lid = tid & 31;
    const int q0 = blockIdx.x * 64;
    const int h  = blockIdx.y;
    const int b  = blockIdx.z;

    const uint32_t bQh = smem_u32(sQh), bQl = smem_u32(sQl);
    const uint32_t bKh = smem_u32(sKh), bVh = smem_u32(sVh);

    const size_t rb = (size_t)b * S_ * N3_ + h * 64;
    const __half* pQh = qkvhi + rb;
    const __half* pQl = qkvlo + rb;
    const __half* pKh = qkvhi + rb + D_;
    const __half* pVh = qkvhi + rb + 2 * D_;

    auto load_tile = [&](uint32_t sb, const __half* p, int row_base) {
        #pragma unroll
        for (int i = 0; i < 4; ++i) {
            int slot = tid + (i << 7);
            int r = slot >> 3, c = slot & 7;
            int gr = row_base + r;
            int sz = (gr < S_) ? 16 : 0;
            const __half* src = p + (size_t)(sz ? gr : 0) * N3_ + c * 8;
            cp_async16(sb + soff(r, c), src, sz);
        }
    };

    load_tile(bQh, pQh, q0);
    load_tile(bQl, pQl, q0);

    float o[8][4];
    #pragma unroll
    for (int dt = 0; dt < 8; ++dt)
        #pragma unroll
        for (int e = 0; e < 4; ++e) o[dt][e] = 0.0f;
    float m0 = -1e30f, m1 = -1e30f, l0 = 0.0f, l1 = 0.0f;

    const int NT = (S_ + 63) / 64;
    for (int kt = 0; kt < NT; ++kt) {
        const int kb = kt * 64;
        load_tile(bKh, pKh, kb);
        load_tile(bVh, pVh, kb);
        cp_commit();
        cp_wait<0>();
        __syncthreads();

        float sc[8][4];
        #pragma unroll
        for (int nt = 0; nt < 8; ++nt)
            #pragma unroll
            for (int e = 0; e < 4; ++e) sc[nt][e] = 0.0f;

        #pragma unroll
        for (int s = 0; s < 4; ++s) {
            uint32_t qh[4], ql[4];
            {
                int r = (wid << 4) + (lid & 15);
                int ch = 2 * s + (lid >> 4);
                uint32_t of = soff(r, ch);
                ldsm_x4(qh[0], qh[1], qh[2], qh[3], bQh + of);
                ldsm_x4(ql[0], ql[1], ql[2], ql[3], bQl + of);
            }
            #pragma unroll
            for (int np = 0; np < 4; ++np) {
                int g2 = lid >> 3;
                int r = (np << 4) + ((g2 >> 1) << 3) + (lid & 7);
                int ch = 2 * s + (g2 & 1);
                uint32_t of = soff(r, ch);
                uint32_t kh[4];
                ldsm_x4(kh[0], kh[1], kh[2], kh[3], bKh + of);
                uint32_t b0[2] = { kh[0], kh[1] }, b1[2] = { kh[2], kh[3] };
                mma_f16(sc[2 * np],     qh, b0);
                mma_f16(sc[2 * np],     ql, b0);
                mma_f16(sc[2 * np + 1], qh, b1);
                mma_f16(sc[2 * np + 1], ql, b1);
            }
        }

        #pragma unroll
        for (int nt = 0; nt < 8; ++nt) {
            int c0i = kb + 8 * nt + 2 * (lid & 3);
            bool v0 = c0i < S_, v1 = (c0i + 1) < S_;
            sc[nt][0] = v0 ? sc[nt][0] * SCALE_ : -1e30f;
            sc[nt][1] = v1 ? sc[nt][1] * SCALE_ : -1e30f;
            sc[nt][2] = v0 ? sc[nt][2] * SCALE_ : -1e30f;
            sc[nt][3] = v1 ? sc[nt][3] * SCALE_ : -1e30f;
        }
        float mx0 = -1e30f, mx1 = -1e30f;
        #pragma unroll
        for (int nt = 0; nt < 8; ++nt) {
            mx0 = fmaxf(mx0, fmaxf(sc[nt][0], sc[nt][1]));
            mx1 = fmaxf(mx1, fmaxf(sc[nt][2], sc[nt][3]));
        }
        mx0 = fmaxf(mx0, __shfl_xor_sync(0xffffffffu, mx0, 1));
        mx0 = fmaxf(mx0, __shfl_xor_sync(0xffffffffu, mx0, 2));
        mx1 = fmaxf(mx1, __shfl_xor_sync(0xffffffffu, mx1, 1));
        mx1 = fmaxf(mx1, __shfl_xor_sync(0xffffffffu, mx1, 2));
        float mn0 = fmaxf(m0, mx0), mn1 = fmaxf(m1, mx1);
        float f0 = __expf(m0 - mn0), f1 = __expf(m1 - mn1);
        float s0 = 0.0f, s1 = 0.0f;
        #pragma unroll
        for (int nt = 0; nt < 8; ++nt) {
            sc[nt][0] = __expf(sc[nt][0] - mn0);
            sc[nt][1] = __expf(sc[nt][1] - mn0);
            sc[nt][2] = __expf(sc[nt][2] - mn1);
            sc[nt][3] = __expf(sc[nt][3] - mn1);
            s0 += sc[nt][0] + sc[nt][1];
            s1 += sc[nt][2] + sc[nt][3];
        }
        s0 += __shfl_xor_sync(0xffffffffu, s0, 1);
        s0 += __shfl_xor_sync(0xffffffffu, s0, 2);
        s1 += __shfl_xor_sync(0xffffffffu, s1, 1);
        s1 += __shfl_xor_sync(0xffffffffu, s1, 2);
        l0 = l0 * f0 + s0;
        l1 = l1 * f1 + s1;
        m0 = mn0; m1 = mn1;
        #pragma unroll
        for (int dt = 0; dt < 8; ++dt) {
            o[dt][0] *= f0; o[dt][1] *= f0;
            o[dt][2] *= f1; o[dt][3] *= f1;
        }

        #pragma unroll
        for (int t = 0; t < 4; ++t) {
            uint32_t ph[4], pl[4];
            split_pack2h(sc[2 * t][0],     sc[2 * t][1],     ph[0], pl[0]);
            split_pack2h(sc[2 * t][2],     sc[2 * t][3],     ph[1], pl[1]);
            split_pack2h(sc[2 * t + 1][0], sc[2 * t + 1][1], ph[2], pl[2]);
            split_pack2h(sc[2 * t + 1][2], sc[2 * t + 1][3], ph[3], pl[3]);
            #pragma unroll
            for (int dp = 0; dp < 4; ++dp) {
                int g2 = lid >> 3;
                int r = (t << 4) + ((g2 & 1) << 3) + (lid & 7);
                int ch = 2 * dp + (g2 >> 1);
                uint32_t of = soff(r, ch);
                uint32_t vh[4];
                ldsm_x4_t(vh[0], vh[1], vh[2], vh[3], bVh + of);
                uint32_t b0[2] = { vh[0], vh[1] }, b1[2] = { vh[2], vh[3] };
                mma_f16(o[2 * dp],     ph, b0);
                mma_f16(o[2 * dp],     pl, b0);
                mma_f16(o[2 * dp + 1], ph, b1);
                mma_f16(o[2 * dp + 1], pl, b1);
            }
        }
        __syncthreads();
    }

    const int qa = q0 + (wid << 4) + (lid >> 2);
    const int qb2 = qa + 8;
    const float inv0 = 1.0f / l0, inv1 = 1.0f / l1;
    #pragma unroll
    for (int dt = 0; dt < 8; ++dt) {
        int col = h * 64 + 8 * dt + 2 * (lid & 3);
        if (qa < S_) {
            uint32_t hh, ll;
            split_pack2h(o[dt][0] * inv0, o[dt][1] * inv0, hh, ll);
            size_t off = (size_t)(b * S_ + qa) * D_ + col;
            *reinterpret_cast<uint32_t*>(&outhi[off]) = hh;
            *reinterpret_cast<uint32_t*>(&outlo[off]) = ll;
        }
        if (qb2 < S_) {
            uint32_t hh, ll;
            split_pack2h(o[dt][2] * inv1, o[dt][3] * inv1, hh, ll);
            size_t off = (size_t)(b * S_ + qb2) * D_ + col;
            *reinterpret_cast<uint32_t*>(&outhi[off]) = hh;
            *reinterpret_cast<uint32_t*>(&outlo[off]) = ll;
        }
    }
}

// ---------------------------------------------------------------------------
extern "C" void kernel_launch(void* const* d_in, const int* in_sizes, int n_in,
                              void* d_out, int out_size)
{
    const float* x     = (const float*)d_in[0];
    const float* w_qkv = (const float*)d_in[1];
    const float* b_qkv = (const float*)d_in[2];
    const float* w_fc  = (const float*)d_in[3];
    const float* b_fc  = (const float*)d_in[4];
    float* out = (float*)d_out;

    __half *xhi, *xlo, *qkvh, *qkvl, *atth, *attl, *wq, *wf;
    cudaGetSymbolAddress((void**)&xhi,  g_xhi);
    cudaGetSymbolAddress((void**)&xlo,  g_xlo);
    cudaGetSymbolAddress((void**)&qkvh, g_qkvhi);
    cudaGetSymbolAddress((void**)&qkvl, g_qkvlo);
    cudaGetSymbolAddress((void**)&atth, g_atthi);
    cudaGetSymbolAddress((void**)&attl, g_attlo);
    cudaGetSymbolAddress((void**)&wq,   g_wqT);
    cudaGetSymbolAddress((void**)&wf,   g_wfT);

    static bool attr_set = false;
    if (!attr_set) {
        cudaFuncSetAttribute(gemm_tc_kernel,
                             cudaFuncAttributeMaxDynamicSharedMemorySize,
                             GEMM_SMEM);
        attr_set = true;
    }

    {
        int n4 = (M_ * D_) / 4;
        split_kernel<<<(n4 + 255) / 256, 256>>>(x, xhi, xlo, n4);
    }
    wconv_kernel<<<(N3_ * D_ + 255) / 256, 256>>>(w_qkv, wq, D_, N3_);
    wconv_kernel<<<(D_ * D_ + 255) / 256, 256>>>(w_fc, wf, D_, D_);

    // 1) QKV projection -> fp16 hi/lo
    gemm_tc_kernel<<<dim3(N3_ / 128, (M_ + 127) / 128), 256, GEMM_SMEM>>>(
        xhi, xlo, wq, b_qkv, nullptr, qkvh, qkvl, M_, N3_, D_);

    // 2) Tensor-core flash attention -> fp16 hi/lo
    attn_tc_kernel<<<dim3((S_ + 63) / 64, H_, B_), 128>>>(qkvh, qkvl, atth, attl);

    // 3) Output projection -> fp32 d_out
    gemm_tc_kernel<<<dim3(D_ / 128, (M_ + 127) / 128), 256, GEMM_SMEM>>>(
        atth, attl, wf, b_fc, out, nullptr, nullptr, M_, D_, D_);
}